// round 1
// baseline (speedup 1.0000x reference)
#include <cuda_runtime.h>
#include <math.h>

#define Hh 128
#define Ww 128
#define HW 16384
#define CC 256

// ---------------- scratch (static __device__, no allocs) ----------------
__device__ float g_buf0[CC * HW];
__device__ float g_buf1[CC * HW];
__device__ float g_buf2[CC * HW];
__device__ float g_pool[32 * HW];
__device__ float g_wt[9 * CC * CC];
__device__ float g_wt_align[9 * CC * CC];
__device__ float g_wt_small[9 * CC * 16];

__constant__ int c_ring[8] = {0, 1, 2, 5, 8, 7, 6, 3};

// ---------------- weight repack: w[OC][CI][NK] -> wt[NK][CI][OCP] ----------------
__global__ void repack_kernel(const float* __restrict__ w, float* __restrict__ wt,
                              int OC, int CI, int NK, int OCP) {
    int idx = blockIdx.x * blockDim.x + threadIdx.x;
    int total = NK * CI * OCP;
    if (idx >= total) return;
    int oc = idx % OCP;
    int ci = (idx / OCP) % CI;
    int k = idx / (OCP * CI);
    wt[idx] = (oc < OC) ? w[((size_t)oc * CI + ci) * NK + k] : 0.f;
}

// OR-conv: rotate ring of 3x3 filters; out channel oc' = o*8 + r
__global__ void repack_or_kernel(const float* __restrict__ w, float* __restrict__ wt) {
    int idx = blockIdx.x * blockDim.x + threadIdx.x;
    if (idx >= 9 * CC * CC) return;
    int ocp = idx % CC;
    int ci = (idx / CC) % CC;
    int d = idx / (CC * CC);
    int o = ocp >> 3, r = ocp & 7;
    int s;
    if (d == 4) {
        s = 4;
    } else {
        int j = 0;
#pragma unroll
        for (int t = 0; t < 8; t++)
            if (c_ring[t] == d) j = t;
        s = c_ring[(j - r + 8) & 7];
    }
    wt[idx] = w[((size_t)o * CC + ci) * 9 + s];
}

// ---------------- big conv / GEMM: OC=256, BM=128 BN=128 BK=8, 8x8 micro ----------------
// wt: [NK][CI][256], X: [CI][HW], Y: [256][HW]
// epi: 0 = Y = acc + bias[m/bias_div]
//      1 = Y = relu(acc + bias[m/bias_div])
//      2 = Y += acc
//      3 = Y = relu(Y + acc)
__global__ void __launch_bounds__(256, 2)
conv_big_kernel(const float* __restrict__ wt, const float* __restrict__ X,
                const float* __restrict__ bias, float* __restrict__ Y,
                int CI, int NK, int epi, int bias_div) {
    __shared__ float Ws[8][128];
    __shared__ float Xs[8][128];

    int y = blockIdx.x;          // image row, BN = 128 = full row
    int bm0 = blockIdx.y * 128;  // output-channel base
    int tid = threadIdx.x;
    int tx = tid & 15;
    int ty = tid >> 4;

    float acc[8][8];
#pragma unroll
    for (int i = 0; i < 8; i++)
#pragma unroll
        for (int j = 0; j < 8; j++) acc[i][j] = 0.f;

    for (int k = 0; k < NK; k++) {
        int dy = (NK == 9) ? (k / 3 - 1) : 0;
        int dx = (NK == 9) ? (k % 3 - 1) : 0;
        int yy = y + dy;
        bool rowok = (yy >= 0 && yy < Hh);

        for (int ci0 = 0; ci0 < CI; ci0 += 8) {
            // load weights tile: Ws[kk][m]
            {
                int kk = tid >> 5;
                int m4 = (tid & 31) * 4;
                const float* p = wt + ((size_t)(k * CI + ci0 + kk)) * 256 + bm0 + m4;
                float4 v = *(const float4*)p;
                *(float4*)&Ws[kk][m4] = v;
            }
            // load input tile (with spatial shift + zero pad)
            {
                int kk = tid >> 5;
                int c0 = tid & 31;
                const float* xrow = X + (size_t)(ci0 + kk) * HW + yy * Ww;
#pragma unroll
                for (int j = 0; j < 4; j++) {
                    int n = c0 + 32 * j;
                    int xx = n + dx;
                    float v = 0.f;
                    if (rowok && xx >= 0 && xx < Ww) v = xrow[xx];
                    Xs[kk][n] = v;
                }
            }
            __syncthreads();
#pragma unroll
            for (int kk = 0; kk < 8; kk++) {
                float a[8], b[8];
                *(float4*)(a) = *(const float4*)&Ws[kk][ty * 4];
                *(float4*)(a + 4) = *(const float4*)&Ws[kk][64 + ty * 4];
                *(float4*)(b) = *(const float4*)&Xs[kk][tx * 4];
                *(float4*)(b + 4) = *(const float4*)&Xs[kk][64 + tx * 4];
#pragma unroll
                for (int i = 0; i < 8; i++)
#pragma unroll
                    for (int j = 0; j < 8; j++) acc[i][j] += a[i] * b[j];
            }
            __syncthreads();
        }
    }

#pragma unroll
    for (int i = 0; i < 8; i++) {
        int m = bm0 + ((i < 4) ? (ty * 4 + i) : (64 + ty * 4 + (i - 4)));
#pragma unroll
        for (int j = 0; j < 8; j++) {
            int n = (j < 4) ? (tx * 4 + j) : (64 + tx * 4 + (j - 4));
            size_t o = (size_t)m * HW + (size_t)y * Ww + n;
            float v = acc[i][j];
            if (epi == 0) {
                v += bias[m / bias_div];
            } else if (epi == 1) {
                v = fmaxf(v + bias[m / bias_div], 0.f);
            } else if (epi == 2) {
                v += Y[o];
            } else {
                v = fmaxf(v + Y[o], 0.f);
            }
            Y[o] = v;
        }
    }
}

// ---------------- small conv: OC <= 16, BM=16 BN=128 BK=8, 4x4 micro, 128 thr ----------------
__global__ void __launch_bounds__(128, 4)
conv_small_kernel(const float* __restrict__ wt, const float* __restrict__ X,
                  const float* __restrict__ bias, float* __restrict__ Y,
                  int CI, int NK, int OC, int relu) {
    __shared__ float Ws[8][16];
    __shared__ float Xs[8][128];

    int y = blockIdx.x;
    int tid = threadIdx.x;
    int tx = tid & 31;  // 0..31 -> n = tx*4+j
    int ty = tid >> 5;  // 0..3  -> m = ty*4+i

    float acc[4][4];
#pragma unroll
    for (int i = 0; i < 4; i++)
#pragma unroll
        for (int j = 0; j < 4; j++) acc[i][j] = 0.f;

    for (int k = 0; k < NK; k++) {
        int dy = (NK == 9) ? (k / 3 - 1) : 0;
        int dx = (NK == 9) ? (k % 3 - 1) : 0;
        int yy = y + dy;
        bool rowok = (yy >= 0 && yy < Hh);

        for (int ci0 = 0; ci0 < CI; ci0 += 8) {
            {
                int kk = tid >> 4;
                int m = tid & 15;
                Ws[kk][m] = wt[((size_t)(k * CI + ci0 + kk)) * 16 + m];
            }
            {
                int kk = tid >> 4;
                int lane = tid & 15;
                const float* xrow = X + (size_t)(ci0 + kk) * HW + yy * Ww;
#pragma unroll
                for (int j = 0; j < 8; j++) {
                    int n = lane + 16 * j;
                    int xx = n + dx;
                    float v = 0.f;
                    if (rowok && xx >= 0 && xx < Ww) v = xrow[xx];
                    Xs[kk][n] = v;
                }
            }
            __syncthreads();
#pragma unroll
            for (int kk = 0; kk < 8; kk++) {
                float a[4], b[4];
                *(float4*)a = *(const float4*)&Ws[kk][ty * 4];
                *(float4*)b = *(const float4*)&Xs[kk][tx * 4];
#pragma unroll
                for (int i = 0; i < 4; i++)
#pragma unroll
                    for (int j = 0; j < 4; j++) acc[i][j] += a[i] * b[j];
            }
            __syncthreads();
        }
    }

#pragma unroll
    for (int i = 0; i < 4; i++) {
        int m = ty * 4 + i;
        if (m < OC) {
            float bv = bias[m];
#pragma unroll
            for (int j = 0; j < 4; j++) {
                int n = tx * 4 + j;
                float v = acc[i][j] + bv;
                if (relu) v = fmaxf(v, 0.f);
                Y[(size_t)m * HW + (size_t)y * Ww + n] = v;
            }
        }
    }
}

// ---------------- anchors + rbox decode ----------------
__global__ void decode_kernel(const float* __restrict__ bbox,  // [5][HW]
                              float* __restrict__ anchors_out, // [HW][5]
                              float* __restrict__ refine_out)  // [HW][5]
{
    int p = blockIdx.x * blockDim.x + threadIdx.x;
    if (p >= HW) return;
    int x = p & 127, yv = p >> 7;
    float ax = x * 8.f + 3.5f;
    float ay = yv * 8.f + 3.5f;
    anchors_out[p * 5 + 0] = ax;
    anchors_out[p * 5 + 1] = ay;
    anchors_out[p * 5 + 2] = 32.f;
    anchors_out[p * 5 + 3] = 32.f;
    anchors_out[p * 5 + 4] = 0.f;

    float dx = bbox[p];
    float dyv = bbox[HW + p];
    float dw = bbox[2 * HW + p];
    float dh = bbox[3 * HW + p];
    float dt = bbox[4 * HW + p];
    const float MR = 13.815510557964274f;
    dw = fminf(fmaxf(dw, -MR), MR);
    dh = fminf(fmaxf(dh, -MR), MR);
    // anchor angle = 0 -> cos=1, sin=0
    float gx = dx * 32.f + ax;
    float gy = dyv * 32.f + ay;
    float gw = 32.f * expf(dw);
    float gh = 32.f * expf(dh);
    const float PI = 3.14159265358979323846f;
    float r = fmodf(dt + PI * 0.25f, PI);
    if (r < 0.f) r += PI;
    float ga = r - PI * 0.25f;
    refine_out[p * 5 + 0] = gx;
    refine_out[p * 5 + 1] = gy;
    refine_out[p * 5 + 2] = gw;
    refine_out[p * 5 + 3] = gh;
    refine_out[p * 5 + 4] = ga;
}

// ---------------- bilinear gather for align-conv tap k: S[c][p] ----------------
__global__ void gather_kernel(const float* __restrict__ feats,
                              const float* __restrict__ refine,  // [HW][5]
                              float* __restrict__ S, int k) {
    int x = threadIdx.x;
    int yv = blockIdx.x;
    int p = yv * Ww + x;

    float axc = refine[p * 5 + 0] * 0.125f;
    float ayc = refine[p * 5 + 1] * 0.125f;
    float aw = refine[p * 5 + 2] * 0.125f;
    float ah = refine[p * 5 + 3] * 0.125f;
    float aa = refine[p * 5 + 4];
    float cs = cosf(aa), sn = sinf(aa);
    float kx = (float)(k % 3 - 1);
    float ky = (float)(k / 3 - 1);
    float ddx = (aw * (1.f / 3.f)) * kx;
    float ddy = (ah * (1.f / 3.f)) * ky;
    float xs = cs * ddx - sn * ddy + axc;
    float ys = sn * ddx + cs * ddy + ayc;

    float x0f = floorf(xs), y0f = floorf(ys);
    float wx1 = xs - x0f, wx0 = 1.f - wx1;
    float wy1 = ys - y0f, wy0 = 1.f - wy1;
    int x0 = (int)x0f, y0 = (int)y0f;

    int idx[4];
    float wg[4];
#pragma unroll
    for (int c = 0; c < 4; c++) {
        int xi = x0 + (c & 1);
        int yi = y0 + (c >> 1);
        float ww = ((c & 1) ? wx1 : wx0) * ((c >> 1) ? wy1 : wy0);
        bool valid = (xi >= 0 && xi < Ww && yi >= 0 && yi < Hh);
        int xc = min(max(xi, 0), Ww - 1);
        int yc = min(max(yi, 0), Hh - 1);
        idx[c] = yc * Ww + xc;
        wg[c] = valid ? ww : 0.f;
    }

    for (int c = 0; c < CC; c++) {
        const float* f = feats + (size_t)c * HW;
        float v = f[idx[0]] * wg[0] + f[idx[1]] * wg[1] + f[idx[2]] * wg[2] + f[idx[3]] * wg[3];
        S[(size_t)c * HW + p] = v;
    }
}

// ---------------- rotation-invariant max pooling over groups of 8 ----------------
__global__ void maxpool8_kernel(const float* __restrict__ orf, float* __restrict__ pooled) {
    int p = blockIdx.x * blockDim.x + threadIdx.x;
    int i = blockIdx.y;
    if (p >= HW) return;
    float m = orf[(size_t)(i * 8) * HW + p];
#pragma unroll
    for (int r = 1; r < 8; r++) m = fmaxf(m, orf[(size_t)(i * 8 + r) * HW + p]);
    pooled[(size_t)i * HW + p] = m;
}

// ---------------- host orchestration ----------------
static void repack(const float* w, float* wt, int OC, int CI, int NK, int OCP) {
    int total = NK * CI * OCP;
    repack_kernel<<<(total + 255) / 256, 256>>>(w, wt, OC, CI, NK, OCP);
}

extern "C" void kernel_launch(void* const* d_in, const int* in_sizes, int n_in,
                              void* d_out, int out_size) {
    (void)in_sizes; (void)n_in; (void)out_size;

    const float* feats = (const float*)d_in[0];
    const float* fam_reg_w0 = (const float*)d_in[1];
    const float* fam_reg_b0 = (const float*)d_in[2];
    const float* fam_reg_w1 = (const float*)d_in[3];
    const float* fam_reg_b1 = (const float*)d_in[4];
    const float* fam_reg_hw = (const float*)d_in[5];
    const float* fam_reg_hb = (const float*)d_in[6];
    const float* fam_cls_w0 = (const float*)d_in[7];
    const float* fam_cls_b0 = (const float*)d_in[8];
    const float* fam_cls_w1 = (const float*)d_in[9];
    const float* fam_cls_b1 = (const float*)d_in[10];
    const float* fam_cls_hw = (const float*)d_in[11];
    const float* fam_cls_hb = (const float*)d_in[12];
    const float* align_w = (const float*)d_in[13];
    const float* align_b = (const float*)d_in[14];
    const float* or_w = (const float*)d_in[15];
    const float* or_b = (const float*)d_in[16];
    const float* odm_reg_w0 = (const float*)d_in[17];
    const float* odm_reg_b0 = (const float*)d_in[18];
    const float* odm_reg_w1 = (const float*)d_in[19];
    const float* odm_reg_b1 = (const float*)d_in[20];
    const float* odm_reg_hw = (const float*)d_in[21];
    const float* odm_reg_hb = (const float*)d_in[22];
    const float* odm_cls_w0 = (const float*)d_in[23];
    const float* odm_cls_b0 = (const float*)d_in[24];
    const float* odm_cls_w1 = (const float*)d_in[25];
    const float* odm_cls_b1 = (const float*)d_in[26];
    const float* odm_cls_hw = (const float*)d_in[27];
    const float* odm_cls_hb = (const float*)d_in[28];

    float* out = (float*)d_out;
    float* o_famcls = out;               // [15][HW]
    float* o_fambbox = out + 245760;     // [5][HW]
    float* o_odmcls = out + 327680;      // [15][HW]
    float* o_odmbbox = out + 573440;     // [5][HW]
    float* o_anchors = out + 655360;     // [HW][5]
    float* o_refine = out + 737280;      // [HW][5]

    float *b0, *b1, *b2, *pool, *wt, *wta, *wts;
    cudaGetSymbolAddress((void**)&b0, g_buf0);
    cudaGetSymbolAddress((void**)&b1, g_buf1);
    cudaGetSymbolAddress((void**)&b2, g_buf2);
    cudaGetSymbolAddress((void**)&pool, g_pool);
    cudaGetSymbolAddress((void**)&wt, g_wt);
    cudaGetSymbolAddress((void**)&wta, g_wt_align);
    cudaGetSymbolAddress((void**)&wts, g_wt_small);

    dim3 gBig(128, 2);
    dim3 gSmall(128, 1);

    // ---- FAM reg branch ----
    repack(fam_reg_w0, wt, 256, 256, 9, 256);
    conv_big_kernel<<<gBig, 256>>>(wt, feats, fam_reg_b0, b0, 256, 9, /*epi*/1, 1);
    repack(fam_reg_w1, wt, 256, 256, 9, 256);
    conv_big_kernel<<<gBig, 256>>>(wt, b0, fam_reg_b1, b1, 256, 9, 1, 1);
    repack(fam_reg_hw, wts, 5, 256, 1, 16);
    conv_small_kernel<<<gSmall, 128>>>(wts, b1, fam_reg_hb, o_fambbox, 256, 1, 5, 0);

    // ---- FAM cls branch ----
    repack(fam_cls_w0, wt, 256, 256, 9, 256);
    conv_big_kernel<<<gBig, 256>>>(wt, feats, fam_cls_b0, b0, 256, 9, 1, 1);
    repack(fam_cls_w1, wt, 256, 256, 9, 256);
    conv_big_kernel<<<gBig, 256>>>(wt, b0, fam_cls_b1, b1, 256, 9, 1, 1);
    repack(fam_cls_hw, wts, 15, 256, 1, 16);
    conv_small_kernel<<<gSmall, 128>>>(wts, b1, fam_cls_hb, o_famcls, 256, 1, 15, 0);

    // ---- anchors + decode ----
    decode_kernel<<<HW / 256, 256>>>(o_fambbox, o_anchors, o_refine);

    // ---- align conv: 9 taps of gather + 1-tap GEMM accumulate ----
    repack(align_w, wta, 256, 256, 9, 256);
    for (int k = 0; k < 9; k++) {
        gather_kernel<<<Hh, Ww>>>(feats, o_refine, b0, k);
        int epi = (k == 0) ? 0 : ((k == 8) ? 3 : 2);
        conv_big_kernel<<<gBig, 256>>>(wta + (size_t)k * 256 * 256, b0, align_b, b1,
                                       256, 1, epi, 1);
    }
    // al in b1

    // ---- OR conv (rotated weights), bias repeated per 8 ----
    {
        int total = 9 * CC * CC;
        repack_or_kernel<<<(total + 255) / 256, 256>>>(or_w, wt);
    }
    conv_big_kernel<<<gBig, 256>>>(wt, b1, or_b, b0, 256, 9, /*epi*/0, /*bias_div*/8);
    // orf in b0

    // ---- rotation-invariant pooling ----
    {
        dim3 g(HW / 256, 32);
        maxpool8_kernel<<<g, 256>>>(b0, pool);
    }

    // ---- ODM cls branch ----
    repack(odm_cls_w0, wt, 256, 32, 9, 256);
    conv_big_kernel<<<gBig, 256>>>(wt, pool, odm_cls_b0, b1, 32, 9, 1, 1);
    repack(odm_cls_w1, wt, 256, 256, 9, 256);
    conv_big_kernel<<<gBig, 256>>>(wt, b1, odm_cls_b1, b2, 256, 9, 1, 1);
    repack(odm_cls_hw, wts, 15, 256, 9, 16);
    conv_small_kernel<<<gSmall, 128>>>(wts, b2, odm_cls_hb, o_odmcls, 256, 9, 15, 0);

    // ---- ODM reg branch ----
    repack(odm_reg_w0, wt, 256, 256, 9, 256);
    conv_big_kernel<<<gBig, 256>>>(wt, b0, odm_reg_b0, b1, 256, 9, 1, 1);
    repack(odm_reg_w1, wt, 256, 256, 9, 256);
    conv_big_kernel<<<gBig, 256>>>(wt, b1, odm_reg_b1, b2, 256, 9, 1, 1);
    repack(odm_reg_hw, wts, 5, 256, 9, 16);
    conv_small_kernel<<<gSmall, 128>>>(wts, b2, odm_reg_hb, o_odmbbox, 256, 9, 5, 0);
}

// round 2
// speedup vs baseline: 1.1209x; 1.1209x over previous
#include <cuda_runtime.h>
#include <math.h>

#define Hh 128
#define Ww 128
#define HW 16384
#define CC 256

typedef unsigned long long ull;

// ---------------- scratch (static __device__, no allocs) ----------------
__device__ float g_buf0[CC * HW];
__device__ float g_buf1[CC * HW];
__device__ float g_buf2[CC * HW];
__device__ float g_pool[32 * HW];
__device__ float g_wt[9 * CC * CC];
__device__ float g_wt_align[9 * CC * CC];
__device__ float g_wt_small[9 * CC * 16];

__constant__ int c_ring[8] = {0, 1, 2, 5, 8, 7, 6, 3};

// ---------------- f32x2 helpers ----------------
__device__ __forceinline__ ull dupf(float v) {
    ull r;
    asm("mov.b64 %0, {%1, %1};" : "=l"(r) : "f"(v));
    return r;
}
__device__ __forceinline__ void ffma2(ull& d, ull a, ull b) {
    asm("fma.rn.f32x2 %0, %1, %2, %0;" : "+l"(d) : "l"(a), "l"(b));
}
__device__ __forceinline__ float2 unpk(ull v) {
    float2 f;
    asm("mov.b64 {%0, %1}, %2;" : "=f"(f.x), "=f"(f.y) : "l"(v));
    return f;
}

// ---------------- weight repack: w[OC][CI][NK] -> wt[NK][CI][OCP] ----------------
__global__ void repack_kernel(const float* __restrict__ w, float* __restrict__ wt,
                              int OC, int CI, int NK, int OCP) {
    int idx = blockIdx.x * blockDim.x + threadIdx.x;
    int total = NK * CI * OCP;
    if (idx >= total) return;
    int oc = idx % OCP;
    int ci = (idx / OCP) % CI;
    int k = idx / (OCP * CI);
    wt[idx] = (oc < OC) ? w[((size_t)oc * CI + ci) * NK + k] : 0.f;
}

// OR-conv: rotate ring of 3x3 filters; out channel oc' = o*8 + r
__global__ void repack_or_kernel(const float* __restrict__ w, float* __restrict__ wt) {
    int idx = blockIdx.x * blockDim.x + threadIdx.x;
    if (idx >= 9 * CC * CC) return;
    int ocp = idx % CC;
    int ci = (idx / CC) % CC;
    int d = idx / (CC * CC);
    int o = ocp >> 3, r = ocp & 7;
    int s;
    if (d == 4) {
        s = 4;
    } else {
        int j = 0;
#pragma unroll
        for (int t = 0; t < 8; t++)
            if (c_ring[t] == d) j = t;
        s = c_ring[(j - r + 8) & 7];
    }
    wt[idx] = w[((size_t)o * CC + ci) * 9 + s];
}

// ---------------- big conv / GEMM: BM=128 BN=128(row) BK=8, 8x8 micro via f32x2 ----------------
// wt: [NK][CI][256], X: [CI][HW], Y: [256][HW]
// epi: 0 = Y = acc + bias[m/bias_div]
//      1 = Y = relu(acc + bias[m/bias_div])
__global__ void __launch_bounds__(256, 2)
conv_big_kernel(const float* __restrict__ wt, const float* __restrict__ X,
                const float* __restrict__ bias, float* __restrict__ Y,
                int CI, int NK, int epi, int bias_div) {
    __shared__ float Ws[8][128];
    __shared__ float Xs[8][128];

    int y = blockIdx.x;          // image row
    int bm0 = blockIdx.y * 128;  // output-channel base
    int tid = threadIdx.x;
    int tx = tid & 15;
    int ty = tid >> 4;

    ull acc2[8][4];
#pragma unroll
    for (int i = 0; i < 8; i++)
#pragma unroll
        for (int j = 0; j < 4; j++) acc2[i][j] = 0ULL;

    for (int k = 0; k < NK; k++) {
        int dy = (NK == 9) ? (k / 3 - 1) : 0;
        int dx = (NK == 9) ? (k % 3 - 1) : 0;
        int yy = y + dy;
        bool rowok = (yy >= 0 && yy < Hh);

        for (int ci0 = 0; ci0 < CI; ci0 += 8) {
            // weights tile: Ws[kk][m]
            {
                int kk = tid >> 5;
                int m4 = (tid & 31) * 4;
                const float* p = wt + ((size_t)(k * CI + ci0 + kk)) * 256 + bm0 + m4;
                *(float4*)&Ws[kk][m4] = *(const float4*)p;
            }
            // input tile (spatial shift + zero pad)
            {
                int kk = tid >> 5;
                int c0 = tid & 31;
                const float* xrow = X + (size_t)(ci0 + kk) * HW + yy * Ww;
#pragma unroll
                for (int j = 0; j < 4; j++) {
                    int n = c0 + 32 * j;
                    int xx = n + dx;
                    float v = 0.f;
                    if (rowok && xx >= 0 && xx < Ww) v = xrow[xx];
                    Xs[kk][n] = v;
                }
            }
            __syncthreads();
#pragma unroll
            for (int kk = 0; kk < 8; kk++) {
                float4 af0 = *(const float4*)&Ws[kk][ty * 4];
                float4 af1 = *(const float4*)&Ws[kk][64 + ty * 4];
                ulonglong2 B0 = *(const ulonglong2*)&Xs[kk][tx * 4];
                ulonglong2 B1 = *(const ulonglong2*)&Xs[kk][64 + tx * 4];
                ull b2[4] = {B0.x, B0.y, B1.x, B1.y};
                float a8[8] = {af0.x, af0.y, af0.z, af0.w, af1.x, af1.y, af1.z, af1.w};
#pragma unroll
                for (int i = 0; i < 8; i++) {
                    ull ad = dupf(a8[i]);
#pragma unroll
                    for (int jp = 0; jp < 4; jp++) ffma2(acc2[i][jp], ad, b2[jp]);
                }
            }
            __syncthreads();
        }
    }

#pragma unroll
    for (int i = 0; i < 8; i++) {
        int m = bm0 + ((i < 4) ? (ty * 4 + i) : (64 + ty * 4 + (i - 4)));
        float bv = bias[m / bias_div];
#pragma unroll
        for (int jp = 0; jp < 4; jp++) {
            float2 v = unpk(acc2[i][jp]);
            int n0 = (jp < 2) ? (tx * 4 + jp * 2) : (64 + tx * 4 + (jp - 2) * 2);
            float v0 = v.x + bv, v1 = v.y + bv;
            if (epi == 1) { v0 = fmaxf(v0, 0.f); v1 = fmaxf(v1, 0.f); }
            *(float2*)&Y[(size_t)m * HW + (size_t)y * Ww + n0] = make_float2(v0, v1);
        }
    }
}

// ---------------- fused deformable align conv ----------------
// Y[oc][p] = relu(bias[oc] + sum_{k,ci} wt[k][ci][oc] * bilinear(feats[ci], coord(p,k)))
__global__ void __launch_bounds__(256, 2)
conv_align_kernel(const float* __restrict__ wt, const float* __restrict__ feats,
                  const float* __restrict__ refine, const float* __restrict__ bias,
                  float* __restrict__ Y) {
    __shared__ float Ws[8][128];
    __shared__ float Xs[8][128];
    __shared__ int s_idx[9][4][128];
    __shared__ float s_w[9][4][128];

    int y = blockIdx.x;
    int bm0 = blockIdx.y * 128;
    int tid = threadIdx.x;
    int tx = tid & 15;
    int ty = tid >> 4;

    // precompute bilinear tables for this row (128 px x 9 taps)
    for (int e = tid; e < 128 * 9; e += 256) {
        int px = e / 9, k = e % 9;
        int p = y * Ww + px;
        float axc = refine[p * 5 + 0] * 0.125f;
        float ayc = refine[p * 5 + 1] * 0.125f;
        float aw = refine[p * 5 + 2] * 0.125f;
        float ah = refine[p * 5 + 3] * 0.125f;
        float aa = refine[p * 5 + 4];
        float cs = cosf(aa), sn = sinf(aa);
        float kx = (float)(k % 3 - 1);
        float ky = (float)(k / 3 - 1);
        float ddx = (aw * (1.f / 3.f)) * kx;
        float ddy = (ah * (1.f / 3.f)) * ky;
        float xs = cs * ddx - sn * ddy + axc;
        float ys = sn * ddx + cs * ddy + ayc;

        float x0f = floorf(xs), y0f = floorf(ys);
        float wx1 = xs - x0f, wx0 = 1.f - wx1;
        float wy1 = ys - y0f, wy0 = 1.f - wy1;
        int x0 = (int)x0f, y0 = (int)y0f;
#pragma unroll
        for (int c = 0; c < 4; c++) {
            int xi = x0 + (c & 1);
            int yi = y0 + (c >> 1);
            float ww = ((c & 1) ? wx1 : wx0) * ((c >> 1) ? wy1 : wy0);
            bool valid = (xi >= 0 && xi < Ww && yi >= 0 && yi < Hh);
            int xc = min(max(xi, 0), Ww - 1);
            int yc = min(max(yi, 0), Hh - 1);
            s_idx[k][c][px] = yc * Ww + xc;
            s_w[k][c][px] = valid ? ww : 0.f;
        }
    }
    __syncthreads();

    ull acc2[8][4];
#pragma unroll
    for (int i = 0; i < 8; i++)
#pragma unroll
        for (int j = 0; j < 4; j++) acc2[i][j] = 0ULL;

    for (int k = 0; k < 9; k++) {
        for (int ci0 = 0; ci0 < CC; ci0 += 8) {
            {
                int kk = tid >> 5;
                int m4 = (tid & 31) * 4;
                const float* p = wt + ((size_t)(k * CC + ci0 + kk)) * 256 + bm0 + m4;
                *(float4*)&Ws[kk][m4] = *(const float4*)p;
            }
            {
                int kk = tid >> 5;
                int c0 = tid & 31;
                const float* f = feats + (size_t)(ci0 + kk) * HW;
#pragma unroll
                for (int j = 0; j < 4; j++) {
                    int n = c0 + 32 * j;
                    float v = f[s_idx[k][0][n]] * s_w[k][0][n]
                            + f[s_idx[k][1][n]] * s_w[k][1][n]
                            + f[s_idx[k][2][n]] * s_w[k][2][n]
                            + f[s_idx[k][3][n]] * s_w[k][3][n];
                    Xs[kk][n] = v;
                }
            }
            __syncthreads();
#pragma unroll
            for (int kk = 0; kk < 8; kk++) {
                float4 af0 = *(const float4*)&Ws[kk][ty * 4];
                float4 af1 = *(const float4*)&Ws[kk][64 + ty * 4];
                ulonglong2 B0 = *(const ulonglong2*)&Xs[kk][tx * 4];
                ulonglong2 B1 = *(const ulonglong2*)&Xs[kk][64 + tx * 4];
                ull b2[4] = {B0.x, B0.y, B1.x, B1.y};
                float a8[8] = {af0.x, af0.y, af0.z, af0.w, af1.x, af1.y, af1.z, af1.w};
#pragma unroll
                for (int i = 0; i < 8; i++) {
                    ull ad = dupf(a8[i]);
#pragma unroll
                    for (int jp = 0; jp < 4; jp++) ffma2(acc2[i][jp], ad, b2[jp]);
                }
            }
            __syncthreads();
        }
    }

#pragma unroll
    for (int i = 0; i < 8; i++) {
        int m = bm0 + ((i < 4) ? (ty * 4 + i) : (64 + ty * 4 + (i - 4)));
        float bv = bias[m];
#pragma unroll
        for (int jp = 0; jp < 4; jp++) {
            float2 v = unpk(acc2[i][jp]);
            int n0 = (jp < 2) ? (tx * 4 + jp * 2) : (64 + tx * 4 + (jp - 2) * 2);
            float v0 = fmaxf(v.x + bv, 0.f), v1 = fmaxf(v.y + bv, 0.f);
            *(float2*)&Y[(size_t)m * HW + (size_t)y * Ww + n0] = make_float2(v0, v1);
        }
    }
}

// ---------------- small conv: OC <= 16, BM=16 BN=128 BK=8, 4x4 micro, 128 thr ----------------
__global__ void __launch_bounds__(128, 4)
conv_small_kernel(const float* __restrict__ wt, const float* __restrict__ X,
                  const float* __restrict__ bias, float* __restrict__ Y,
                  int CI, int NK, int OC, int relu) {
    __shared__ float Ws[8][16];
    __shared__ float Xs[8][128];

    int y = blockIdx.x;
    int tid = threadIdx.x;
    int tx = tid & 31;
    int ty = tid >> 5;

    float acc[4][4];
#pragma unroll
    for (int i = 0; i < 4; i++)
#pragma unroll
        for (int j = 0; j < 4; j++) acc[i][j] = 0.f;

    for (int k = 0; k < NK; k++) {
        int dy = (NK == 9) ? (k / 3 - 1) : 0;
        int dx = (NK == 9) ? (k % 3 - 1) : 0;
        int yy = y + dy;
        bool rowok = (yy >= 0 && yy < Hh);

        for (int ci0 = 0; ci0 < CI; ci0 += 8) {
            {
                int kk = tid >> 4;
                int m = tid & 15;
                Ws[kk][m] = wt[((size_t)(k * CI + ci0 + kk)) * 16 + m];
            }
            {
                int kk = tid >> 4;
                int lane = tid & 15;
                const float* xrow = X + (size_t)(ci0 + kk) * HW + yy * Ww;
#pragma unroll
                for (int j = 0; j < 8; j++) {
                    int n = lane + 16 * j;
                    int xx = n + dx;
                    float v = 0.f;
                    if (rowok && xx >= 0 && xx < Ww) v = xrow[xx];
                    Xs[kk][n] = v;
                }
            }
            __syncthreads();
#pragma unroll
            for (int kk = 0; kk < 8; kk++) {
                float a[4], b[4];
                *(float4*)a = *(const float4*)&Ws[kk][ty * 4];
                *(float4*)b = *(const float4*)&Xs[kk][tx * 4];
#pragma unroll
                for (int i = 0; i < 4; i++)
#pragma unroll
                    for (int j = 0; j < 4; j++) acc[i][j] += a[i] * b[j];
            }
            __syncthreads();
        }
    }

#pragma unroll
    for (int i = 0; i < 4; i++) {
        int m = ty * 4 + i;
        if (m < OC) {
            float bv = bias[m];
#pragma unroll
            for (int j = 0; j < 4; j++) {
                int n = tx * 4 + j;
                float v = acc[i][j] + bv;
                if (relu) v = fmaxf(v, 0.f);
                Y[(size_t)m * HW + (size_t)y * Ww + n] = v;
            }
        }
    }
}

// ---------------- anchors + rbox decode ----------------
__global__ void decode_kernel(const float* __restrict__ bbox,  // [5][HW]
                              float* __restrict__ anchors_out, // [HW][5]
                              float* __restrict__ refine_out)  // [HW][5]
{
    int p = blockIdx.x * blockDim.x + threadIdx.x;
    if (p >= HW) return;
    int x = p & 127, yv = p >> 7;
    float ax = x * 8.f + 3.5f;
    float ay = yv * 8.f + 3.5f;
    anchors_out[p * 5 + 0] = ax;
    anchors_out[p * 5 + 1] = ay;
    anchors_out[p * 5 + 2] = 32.f;
    anchors_out[p * 5 + 3] = 32.f;
    anchors_out[p * 5 + 4] = 0.f;

    float dx = bbox[p];
    float dyv = bbox[HW + p];
    float dw = bbox[2 * HW + p];
    float dh = bbox[3 * HW + p];
    float dt = bbox[4 * HW + p];
    const float MR = 13.815510557964274f;
    dw = fminf(fmaxf(dw, -MR), MR);
    dh = fminf(fmaxf(dh, -MR), MR);
    float gx = dx * 32.f + ax;
    float gy = dyv * 32.f + ay;
    float gw = 32.f * expf(dw);
    float gh = 32.f * expf(dh);
    const float PI = 3.14159265358979323846f;
    float r = fmodf(dt + PI * 0.25f, PI);
    if (r < 0.f) r += PI;
    float ga = r - PI * 0.25f;
    refine_out[p * 5 + 0] = gx;
    refine_out[p * 5 + 1] = gy;
    refine_out[p * 5 + 2] = gw;
    refine_out[p * 5 + 3] = gh;
    refine_out[p * 5 + 4] = ga;
}

// ---------------- rotation-invariant max pooling over groups of 8 ----------------
__global__ void maxpool8_kernel(const float* __restrict__ orf, float* __restrict__ pooled) {
    int p = blockIdx.x * blockDim.x + threadIdx.x;
    int i = blockIdx.y;
    if (p >= HW) return;
    float m = orf[(size_t)(i * 8) * HW + p];
#pragma unroll
    for (int r = 1; r < 8; r++) m = fmaxf(m, orf[(size_t)(i * 8 + r) * HW + p]);
    pooled[(size_t)i * HW + p] = m;
}

// ---------------- host orchestration ----------------
static void repack(const float* w, float* wt, int OC, int CI, int NK, int OCP) {
    int total = NK * CI * OCP;
    repack_kernel<<<(total + 255) / 256, 256>>>(w, wt, OC, CI, NK, OCP);
}

extern "C" void kernel_launch(void* const* d_in, const int* in_sizes, int n_in,
                              void* d_out, int out_size) {
    (void)in_sizes; (void)n_in; (void)out_size;

    const float* feats = (const float*)d_in[0];
    const float* fam_reg_w0 = (const float*)d_in[1];
    const float* fam_reg_b0 = (const float*)d_in[2];
    const float* fam_reg_w1 = (const float*)d_in[3];
    const float* fam_reg_b1 = (const float*)d_in[4];
    const float* fam_reg_hw = (const float*)d_in[5];
    const float* fam_reg_hb = (const float*)d_in[6];
    const float* fam_cls_w0 = (const float*)d_in[7];
    const float* fam_cls_b0 = (const float*)d_in[8];
    const float* fam_cls_w1 = (const float*)d_in[9];
    const float* fam_cls_b1 = (const float*)d_in[10];
    const float* fam_cls_hw = (const float*)d_in[11];
    const float* fam_cls_hb = (const float*)d_in[12];
    const float* align_w = (const float*)d_in[13];
    const float* align_b = (const float*)d_in[14];
    const float* or_w = (const float*)d_in[15];
    const float* or_b = (const float*)d_in[16];
    const float* odm_reg_w0 = (const float*)d_in[17];
    const float* odm_reg_b0 = (const float*)d_in[18];
    const float* odm_reg_w1 = (const float*)d_in[19];
    const float* odm_reg_b1 = (const float*)d_in[20];
    const float* odm_reg_hw = (const float*)d_in[21];
    const float* odm_reg_hb = (const float*)d_in[22];
    const float* odm_cls_w0 = (const float*)d_in[23];
    const float* odm_cls_b0 = (const float*)d_in[24];
    const float* odm_cls_w1 = (const float*)d_in[25];
    const float* odm_cls_b1 = (const float*)d_in[26];
    const float* odm_cls_hw = (const float*)d_in[27];
    const float* odm_cls_hb = (const float*)d_in[28];

    float* out = (float*)d_out;
    float* o_famcls = out;               // [15][HW]
    float* o_fambbox = out + 245760;     // [5][HW]
    float* o_odmcls = out + 327680;      // [15][HW]
    float* o_odmbbox = out + 573440;     // [5][HW]
    float* o_anchors = out + 655360;     // [HW][5]
    float* o_refine = out + 737280;      // [HW][5]

    float *b0, *b1, *b2, *pool, *wt, *wta, *wts;
    cudaGetSymbolAddress((void**)&b0, g_buf0);
    cudaGetSymbolAddress((void**)&b1, g_buf1);
    cudaGetSymbolAddress((void**)&b2, g_buf2);
    cudaGetSymbolAddress((void**)&pool, g_pool);
    cudaGetSymbolAddress((void**)&wt, g_wt);
    cudaGetSymbolAddress((void**)&wta, g_wt_align);
    cudaGetSymbolAddress((void**)&wts, g_wt_small);

    dim3 gBig(128, 2);
    dim3 gSmall(128, 1);

    // ---- FAM reg branch ----
    repack(fam_reg_w0, wt, 256, 256, 9, 256);
    conv_big_kernel<<<gBig, 256>>>(wt, feats, fam_reg_b0, b0, 256, 9, 1, 1);
    repack(fam_reg_w1, wt, 256, 256, 9, 256);
    conv_big_kernel<<<gBig, 256>>>(wt, b0, fam_reg_b1, b1, 256, 9, 1, 1);
    repack(fam_reg_hw, wts, 5, 256, 1, 16);
    conv_small_kernel<<<gSmall, 128>>>(wts, b1, fam_reg_hb, o_fambbox, 256, 1, 5, 0);

    // ---- FAM cls branch ----
    repack(fam_cls_w0, wt, 256, 256, 9, 256);
    conv_big_kernel<<<gBig, 256>>>(wt, feats, fam_cls_b0, b0, 256, 9, 1, 1);
    repack(fam_cls_w1, wt, 256, 256, 9, 256);
    conv_big_kernel<<<gBig, 256>>>(wt, b0, fam_cls_b1, b1, 256, 9, 1, 1);
    repack(fam_cls_hw, wts, 15, 256, 1, 16);
    conv_small_kernel<<<gSmall, 128>>>(wts, b1, fam_cls_hb, o_famcls, 256, 1, 15, 0);

    // ---- anchors + decode ----
    decode_kernel<<<HW / 256, 256>>>(o_fambbox, o_anchors, o_refine);

    // ---- fused deformable align conv ----
    repack(align_w, wta, 256, 256, 9, 256);
    conv_align_kernel<<<gBig, 256>>>(wta, feats, o_refine, align_b, b1);
    // al in b1

    // ---- OR conv (rotated weights), bias repeated per 8 ----
    {
        int total = 9 * CC * CC;
        repack_or_kernel<<<(total + 255) / 256, 256>>>(or_w, wt);
    }
    conv_big_kernel<<<gBig, 256>>>(wt, b1, or_b, b0, 256, 9, /*epi*/0, /*bias_div*/8);
    // orf in b0

    // ---- rotation-invariant pooling ----
    {
        dim3 g(HW / 256, 32);
        maxpool8_kernel<<<g, 256>>>(b0, pool);
    }

    // ---- ODM cls branch ----
    repack(odm_cls_w0, wt, 256, 32, 9, 256);
    conv_big_kernel<<<gBig, 256>>>(wt, pool, odm_cls_b0, b1, 32, 9, 1, 1);
    repack(odm_cls_w1, wt, 256, 256, 9, 256);
    conv_big_kernel<<<gBig, 256>>>(wt, b1, odm_cls_b1, b2, 256, 9, 1, 1);
    repack(odm_cls_hw, wts, 15, 256, 9, 16);
    conv_small_kernel<<<gSmall, 128>>>(wts, b2, odm_cls_hb, o_odmcls, 256, 9, 15, 0);

    // ---- ODM reg branch ----
    repack(odm_reg_w0, wt, 256, 256, 9, 256);
    conv_big_kernel<<<gBig, 256>>>(wt, b0, odm_reg_b0, b1, 256, 9, 1, 1);
    repack(odm_reg_w1, wt, 256, 256, 9, 256);
    conv_big_kernel<<<gBig, 256>>>(wt, b1, odm_reg_b1, b2, 256, 9, 1, 1);
    repack(odm_reg_hw, wts, 5, 256, 9, 16);
    conv_small_kernel<<<gSmall, 128>>>(wts, b2, odm_reg_hb, o_odmbbox, 256, 9, 5, 0);
}

// round 5
// speedup vs baseline: 1.6895x; 1.5072x over previous
#include <cuda_runtime.h>
#include <cuda_bf16.h>
#include <math.h>
#include <stdint.h>

#define Hh 128
#define Ww 128
#define HW 16384
#define CC 256

typedef unsigned long long ull;

// ---------------- scratch (static __device__, no allocs) ----------------
__device__ float g_buf0[CC * HW];
__device__ float g_buf1[CC * HW];
__device__ float g_buf2[CC * HW];
__device__ float g_pool[32 * HW];
__device__ float g_wt_align[9 * CC * CC];
__device__ float g_wt_small[9 * CC * 16];
__device__ unsigned char g_wpack[36 * 65536];  // packed bf16 hi/lo weight tiles
__device__ __nv_bfloat16 g_pah[CC * HW];
__device__ __nv_bfloat16 g_pal[CC * HW];
__device__ __nv_bfloat16 g_pbh[CC * HW];
__device__ __nv_bfloat16 g_pbl[CC * HW];
__device__ __nv_bfloat16 g_pch[32 * HW];
__device__ __nv_bfloat16 g_pcl[32 * HW];

__constant__ int c_ring[8] = {0, 1, 2, 5, 8, 7, 6, 3};

// ---------------- f32x2 helpers (align kernel) ----------------
__device__ __forceinline__ ull dupf(float v) {
    ull r;
    asm("mov.b64 %0, {%1, %1};" : "=l"(r) : "f"(v));
    return r;
}
__device__ __forceinline__ void ffma2(ull& d, ull a, ull b) {
    asm("fma.rn.f32x2 %0, %1, %2, %0;" : "+l"(d) : "l"(a), "l"(b));
}
__device__ __forceinline__ float2 unpk(ull v) {
    float2 f;
    asm("mov.b64 {%0, %1}, %2;" : "=f"(f.x), "=f"(f.y) : "l"(v));
    return f;
}

// ---------------- mma / ldmatrix helpers (sm_80-class, valid on compute_103) --------
__device__ __forceinline__ uint32_t smem_u32(const void* p) {
    uint32_t a;
    asm("{ .reg .u64 t; cvta.to.shared.u64 t, %1; cvt.u32.u64 %0, t; }" : "=r"(a) : "l"(p));
    return a;
}
__device__ __forceinline__ void ldm4(uint32_t* r, uint32_t addr) {
    asm volatile("ldmatrix.sync.aligned.m8n8.x4.shared.b16 {%0,%1,%2,%3}, [%4];"
                 : "=r"(r[0]), "=r"(r[1]), "=r"(r[2]), "=r"(r[3]) : "r"(addr));
}
__device__ __forceinline__ void mma_bf16(float* c, const uint32_t* a, uint32_t b0, uint32_t b1) {
    asm volatile(
        "mma.sync.aligned.m16n8k16.row.col.f32.bf16.bf16.f32 "
        "{%0,%1,%2,%3}, {%4,%5,%6,%7}, {%8,%9}, {%0,%1,%2,%3};"
        : "+f"(c[0]), "+f"(c[1]), "+f"(c[2]), "+f"(c[3])
        : "r"(a[0]), "r"(a[1]), "r"(a[2]), "r"(a[3]), "r"(b0), "r"(b1));
}

// ---------------- weight repack to packed bf16 hi/lo SW128 tiles ----------------
// w: [256][CI][9] fp32 -> wpack: [sub][half(2)][hi/lo(2)][128oc x 64kc bf16, SW128]
__global__ void repack_tc_kernel(const float* __restrict__ w,
                                 unsigned char* __restrict__ wp, int CI) {
    int ncc = (CI + 63) >> 6;
    int total = 9 * ncc * 16384;
    int idx = blockIdx.x * blockDim.x + threadIdx.x;
    if (idx >= total) return;
    int kc = idx & 63;
    int oc = (idx >> 6) & 255;
    int sub = idx >> 14;
    int tap = sub / ncc, cc2 = sub % ncc;
    int ci = (cc2 << 6) + kc;
    float v = (ci < CI) ? w[((size_t)oc * CI + ci) * 9 + tap] : 0.f;
    __nv_bfloat16 hb = __float2bfloat16(v);
    __nv_bfloat16 lb = __float2bfloat16(v - __bfloat162float(hb));
    int half = oc >> 7, ocl = oc & 127;
    uint32_t ofs = (uint32_t)ocl * 128u + (((uint32_t)kc * 2u) ^ (((uint32_t)ocl & 7u) << 4));
    size_t base = (size_t)sub * 65536 + (size_t)(half * 2) * 16384;
    *(unsigned short*)(wp + base + ofs) = *(unsigned short*)&hb;
    *(unsigned short*)(wp + base + 16384 + ofs) = *(unsigned short*)&lb;
}

// OR-conv variant: rotated ring source tap
__global__ void repack_or_tc_kernel(const float* __restrict__ w,
                                    unsigned char* __restrict__ wp) {
    int idx = blockIdx.x * blockDim.x + threadIdx.x;
    if (idx >= 36 * 16384) return;
    int kc = idx & 63;
    int oc = (idx >> 6) & 255;
    int sub = idx >> 14;
    int tap = sub >> 2, cc2 = sub & 3;
    int ci = (cc2 << 6) + kc;
    int o = oc >> 3, r = oc & 7;
    int s;
    if (tap == 4) {
        s = 4;
    } else {
        int j = 0;
#pragma unroll
        for (int t = 0; t < 8; t++)
            if (c_ring[t] == tap) j = t;
        s = c_ring[(j - r + 8) & 7];
    }
    float v = w[((size_t)o * CC + ci) * 9 + s];
    __nv_bfloat16 hb = __float2bfloat16(v);
    __nv_bfloat16 lb = __float2bfloat16(v - __bfloat162float(hb));
    int half = oc >> 7, ocl = oc & 127;
    uint32_t ofs = (uint32_t)ocl * 128u + (((uint32_t)kc * 2u) ^ (((uint32_t)ocl & 7u) << 4));
    size_t base = (size_t)sub * 65536 + (size_t)(half * 2) * 16384;
    *(unsigned short*)(wp + base + ofs) = *(unsigned short*)&hb;
    *(unsigned short*)(wp + base + 16384 + ofs) = *(unsigned short*)&lb;
}

// ---------------- fp32 -> bf16 hi/lo pair conversion ----------------
__global__ void cvt_pair_kernel(const float* __restrict__ x,
                                __nv_bfloat16* __restrict__ h,
                                __nv_bfloat16* __restrict__ l, int n) {
    int i = blockIdx.x * blockDim.x + threadIdx.x;
    if (i >= n) return;
    float v = x[i];
    __nv_bfloat16 hb = __float2bfloat16(v);
    h[i] = hb;
    l[i] = __float2bfloat16(v - __bfloat162float(hb));
}

// ---------------- HMMA conv: 3x3 (or 1x1-ish via zero pad), OC=256, one row/CTA ----
// A (weights) pre-packed SW128 bf16 hi/lo; B (acts) bf16 hi/lo tensors [CI][HW].
// D[256 x 128] fp32 in registers; split product: Ah*Bh + Ah*Bl + Al*Bh.
#define SMEMH 98304
__global__ void __launch_bounds__(256, 1)
conv_hmma_kernel(const unsigned char* __restrict__ wpack,
                 const __nv_bfloat16* __restrict__ Xh,
                 const __nv_bfloat16* __restrict__ Xl,
                 const float* __restrict__ bias,
                 float* __restrict__ Y,
                 __nv_bfloat16* __restrict__ Yh, __nv_bfloat16* __restrict__ Yl,
                 int CI, int relu, int bias_div, int writeF, int writeP) {
    extern __shared__ unsigned char sm[];
    uint32_t aA = smem_u32(sm);
    uint32_t aB = aA + 65536;
    unsigned char* smA = sm;
    unsigned char* smB = sm + 65536;

    int tid = threadIdx.x;
    int y = blockIdx.x;
    int lane = tid & 31, wid = tid >> 5;
    int wm = wid >> 1, wn = wid & 1;
    int mbase = wm * 64;
    int half = mbase >> 7;
    int mrow0 = mbase & 127;
    int nbase = wn * 64;

    float acc[4][8][4];
#pragma unroll
    for (int a = 0; a < 4; a++)
#pragma unroll
        for (int b = 0; b < 8; b++)
#pragma unroll
            for (int c = 0; c < 4; c++) acc[a][b][c] = 0.f;

    int ncc = (CI + 63) >> 6;
    int role = tid >> 7;
    int px = tid & 127;

    int lrow = (lane & 7) + ((lane >> 3) & 1) * 8;  // 0..15
    int lcol16 = (lane >> 4) * 16;                  // 0 or 16

    int sub = 0;
    for (int tap = 0; tap < 9; tap++) {
        int dy = tap / 3 - 1, dx = tap % 3 - 1;
        int ysrc = y + dy, xsrc = px + dx;
        bool ok = (ysrc >= 0) && (ysrc < Hh) && (xsrc >= 0) && (xsrc < Ww);
        const __nv_bfloat16* xc = (role ? Xl : Xh) + (size_t)ysrc * Ww + xsrc;
        for (int cc2 = 0; cc2 < ncc; cc2++, sub++) {
            int ci0 = cc2 << 6;
            // A: copy 64KB pre-packed tiles
            {
                const uint4* src = (const uint4*)(wpack + (size_t)sub * 65536);
                uint4* dst = (uint4*)smA;
#pragma unroll
                for (int i = 0; i < 16; i++) dst[tid + i * 256] = src[tid + i * 256];
            }
            // B: build im2col tile (hi or lo per role), SW128 [128px x 64k]
            {
                unsigned char* bT = smB + role * 16384;
#pragma unroll
                for (int ch = 0; ch < 8; ch++) {
                    uint32_t pk[4];
#pragma unroll
                    for (int q = 0; q < 4; q++) {
                        uint32_t v0 = 0, v1 = 0;
                        int c0 = ci0 + ch * 8 + q * 2;
                        if (ok && c0 < CI) v0 = *(const unsigned short*)(xc + (size_t)c0 * HW);
                        if (ok && c0 + 1 < CI) v1 = *(const unsigned short*)(xc + (size_t)(c0 + 1) * HW);
                        pk[q] = v0 | (v1 << 16);
                    }
                    uint32_t ofs = (uint32_t)px * 128u +
                                   (((uint32_t)ch << 4) ^ (((uint32_t)px & 7u) << 4));
                    *(uint4*)(bT + ofs) = make_uint4(pk[0], pk[1], pk[2], pk[3]);
                }
            }
            __syncthreads();
            // compute: 4 k16 steps
#pragma unroll
            for (int ks = 0; ks < 4; ks++) {
                int kb = ks * 32;
                uint32_t Ah[4][4], Al[4][4];
#pragma unroll
                for (int mt = 0; mt < 4; mt++) {
                    int row = mrow0 + mt * 16 + lrow;
                    uint32_t roff = (uint32_t)row * 128u +
                                    (((uint32_t)(kb + lcol16)) ^ (((uint32_t)row & 7u) << 4));
                    ldm4(Ah[mt], aA + (half * 2 + 0) * 16384 + roff);
                    ldm4(Al[mt], aA + (half * 2 + 1) * 16384 + roff);
                }
                // Bh first (used by Ah and Al), then Bl (used by Ah)
                {
                    uint32_t Bh[4][4];
#pragma unroll
                    for (int nt = 0; nt < 4; nt++) {
                        int row = nbase + nt * 16 + lrow;
                        uint32_t roff = (uint32_t)row * 128u +
                                        (((uint32_t)(kb + lcol16)) ^ (((uint32_t)row & 7u) << 4));
                        ldm4(Bh[nt], aB + roff);
                    }
#pragma unroll
                    for (int mt = 0; mt < 4; mt++)
#pragma unroll
                        for (int nt = 0; nt < 4; nt++) {
                            mma_bf16(acc[mt][nt * 2 + 0], Ah[mt], Bh[nt][0], Bh[nt][2]);
                            mma_bf16(acc[mt][nt * 2 + 0], Al[mt], Bh[nt][0], Bh[nt][2]);
                            mma_bf16(acc[mt][nt * 2 + 1], Ah[mt], Bh[nt][1], Bh[nt][3]);
                            mma_bf16(acc[mt][nt * 2 + 1], Al[mt], Bh[nt][1], Bh[nt][3]);
                        }
                }
                {
                    uint32_t Bl[4][4];
#pragma unroll
                    for (int nt = 0; nt < 4; nt++) {
                        int row = nbase + nt * 16 + lrow;
                        uint32_t roff = (uint32_t)row * 128u +
                                        (((uint32_t)(kb + lcol16)) ^ (((uint32_t)row & 7u) << 4));
                        ldm4(Bl[nt], aB + 16384 + roff);
                    }
#pragma unroll
                    for (int mt = 0; mt < 4; mt++)
#pragma unroll
                        for (int nt = 0; nt < 4; nt++) {
                            mma_bf16(acc[mt][nt * 2 + 0], Ah[mt], Bl[nt][0], Bl[nt][2]);
                            mma_bf16(acc[mt][nt * 2 + 1], Ah[mt], Bl[nt][1], Bl[nt][3]);
                        }
                }
            }
            __syncthreads();
        }
    }

    // epilogue: D frag -> gmem (fp32 and/or bf16 hi/lo pair)
    int qr = lane >> 2, qc = lane & 3;
#pragma unroll
    for (int mt = 0; mt < 4; mt++) {
#pragma unroll
        for (int nf = 0; nf < 8; nf++) {
#pragma unroll
            for (int p = 0; p < 2; p++) {
                int oc = mbase + mt * 16 + qr + p * 8;
                int pxo = nbase + nf * 8 + qc * 2;
                float bv = bias[oc / bias_div];
                float v0 = acc[mt][nf][p * 2 + 0] + bv;
                float v1 = acc[mt][nf][p * 2 + 1] + bv;
                if (relu) { v0 = fmaxf(v0, 0.f); v1 = fmaxf(v1, 0.f); }
                size_t o = (size_t)oc * HW + (size_t)y * Ww + pxo;
                if (writeF) *(float2*)(Y + o) = make_float2(v0, v1);
                if (writeP) {
                    __nv_bfloat16 h0 = __float2bfloat16(v0), h1 = __float2bfloat16(v1);
                    __nv_bfloat16 l0 = __float2bfloat16(v0 - __bfloat162float(h0));
                    __nv_bfloat16 l1 = __float2bfloat16(v1 - __bfloat162float(h1));
                    unsigned short u0 = *(unsigned short*)&h0, u1 = *(unsigned short*)&h1;
                    unsigned short w0 = *(unsigned short*)&l0, w1 = *(unsigned short*)&l1;
                    *(uint32_t*)(Yh + o) = (uint32_t)u0 | ((uint32_t)u1 << 16);
                    *(uint32_t*)(Yl + o) = (uint32_t)w0 | ((uint32_t)w1 << 16);
                }
            }
        }
    }
}

// ---------------- generic float repack (align + small heads) ----------------
__global__ void repack_kernel(const float* __restrict__ w, float* __restrict__ wt,
                              int OC, int CI, int NK, int OCP) {
    int idx = blockIdx.x * blockDim.x + threadIdx.x;
    int total = NK * CI * OCP;
    if (idx >= total) return;
    int oc = idx % OCP;
    int ci = (idx / OCP) % CI;
    int k = idx / (OCP * CI);
    wt[idx] = (oc < OC) ? w[((size_t)oc * CI + ci) * NK + k] : 0.f;
}

// ---------------- fused deformable align conv (FFMA2), writes bf16 pair ----------
__global__ void __launch_bounds__(256, 2)
conv_align_kernel(const float* __restrict__ wt, const float* __restrict__ feats,
                  const float* __restrict__ refine, const float* __restrict__ bias,
                  __nv_bfloat16* __restrict__ Yh, __nv_bfloat16* __restrict__ Yl) {
    __shared__ float Ws[8][128];
    __shared__ float Xs[8][128];
    __shared__ int s_idx[9][4][128];
    __shared__ float s_w[9][4][128];

    int y = blockIdx.x;
    int bm0 = blockIdx.y * 128;
    int tid = threadIdx.x;
    int tx = tid & 15;
    int ty = tid >> 4;

    for (int e = tid; e < 128 * 9; e += 256) {
        int px = e / 9, k = e % 9;
        int p = y * Ww + px;
        float axc = refine[p * 5 + 0] * 0.125f;
        float ayc = refine[p * 5 + 1] * 0.125f;
        float aw = refine[p * 5 + 2] * 0.125f;
        float ah = refine[p * 5 + 3] * 0.125f;
        float aa = refine[p * 5 + 4];
        float cs = cosf(aa), sn = sinf(aa);
        float kx = (float)(k % 3 - 1);
        float ky = (float)(k / 3 - 1);
        float ddx = (aw * (1.f / 3.f)) * kx;
        float ddy = (ah * (1.f / 3.f)) * ky;
        float xs = cs * ddx - sn * ddy + axc;
        float ys = sn * ddx + cs * ddy + ayc;

        float x0f = floorf(xs), y0f = floorf(ys);
        float wx1 = xs - x0f, wx0 = 1.f - wx1;
        float wy1 = ys - y0f, wy0 = 1.f - wy1;
        int x0 = (int)x0f, y0 = (int)y0f;
#pragma unroll
        for (int c = 0; c < 4; c++) {
            int xi = x0 + (c & 1);
            int yi = y0 + (c >> 1);
            float ww = ((c & 1) ? wx1 : wx0) * ((c >> 1) ? wy1 : wy0);
            bool valid = (xi >= 0 && xi < Ww && yi >= 0 && yi < Hh);
            int xcv = min(max(xi, 0), Ww - 1);
            int ycv = min(max(yi, 0), Hh - 1);
            s_idx[k][c][px] = ycv * Ww + xcv;
            s_w[k][c][px] = valid ? ww : 0.f;
        }
    }
    __syncthreads();

    ull acc2[8][4];
#pragma unroll
    for (int i = 0; i < 8; i++)
#pragma unroll
        for (int j = 0; j < 4; j++) acc2[i][j] = 0ULL;

    for (int k = 0; k < 9; k++) {
        for (int ci0 = 0; ci0 < CC; ci0 += 8) {
            {
                int kk = tid >> 5;
                int m4 = (tid & 31) * 4;
                const float* p = wt + ((size_t)(k * CC + ci0 + kk)) * 256 + bm0 + m4;
                *(float4*)&Ws[kk][m4] = *(const float4*)p;
            }
            {
                int kk = tid >> 5;
                int c0 = tid & 31;
                const float* f = feats + (size_t)(ci0 + kk) * HW;
#pragma unroll
                for (int j = 0; j < 4; j++) {
                    int n = c0 + 32 * j;
                    float v = f[s_idx[k][0][n]] * s_w[k][0][n]
                            + f[s_idx[k][1][n]] * s_w[k][1][n]
                            + f[s_idx[k][2][n]] * s_w[k][2][n]
                            + f[s_idx[k][3][n]] * s_w[k][3][n];
                    Xs[kk][n] = v;
                }
            }
            __syncthreads();
#pragma unroll
            for (int kk = 0; kk < 8; kk++) {
                float4 af0 = *(const float4*)&Ws[kk][ty * 4];
                float4 af1 = *(const float4*)&Ws[kk][64 + ty * 4];
                ulonglong2 B0 = *(const ulonglong2*)&Xs[kk][tx * 4];
                ulonglong2 B1 = *(const ulonglong2*)&Xs[kk][64 + tx * 4];
                ull b2[4] = {B0.x, B0.y, B1.x, B1.y};
                float a8[8] = {af0.x, af0.y, af0.z, af0.w, af1.x, af1.y, af1.z, af1.w};
#pragma unroll
                for (int i = 0; i < 8; i++) {
                    ull ad = dupf(a8[i]);
#pragma unroll
                    for (int jp = 0; jp < 4; jp++) ffma2(acc2[i][jp], ad, b2[jp]);
                }
            }
            __syncthreads();
        }
    }

#pragma unroll
    for (int i = 0; i < 8; i++) {
        int m = bm0 + ((i < 4) ? (ty * 4 + i) : (64 + ty * 4 + (i - 4)));
        float bv = bias[m];
#pragma unroll
        for (int jp = 0; jp < 4; jp++) {
            float2 v = unpk(acc2[i][jp]);
            int n0 = (jp < 2) ? (tx * 4 + jp * 2) : (64 + tx * 4 + (jp - 2) * 2);
            float v0 = fmaxf(v.x + bv, 0.f), v1 = fmaxf(v.y + bv, 0.f);
            __nv_bfloat16 h0 = __float2bfloat16(v0), h1 = __float2bfloat16(v1);
            __nv_bfloat16 l0 = __float2bfloat16(v0 - __bfloat162float(h0));
            __nv_bfloat16 l1 = __float2bfloat16(v1 - __bfloat162float(h1));
            size_t o = (size_t)m * HW + (size_t)y * Ww + n0;
            unsigned short u0 = *(unsigned short*)&h0, u1 = *(unsigned short*)&h1;
            unsigned short w0 = *(unsigned short*)&l0, w1 = *(unsigned short*)&l1;
            *(uint32_t*)(Yh + o) = (uint32_t)u0 | ((uint32_t)u1 << 16);
            *(uint32_t*)(Yl + o) = (uint32_t)w0 | ((uint32_t)w1 << 16);
        }
    }
}

// ---------------- small conv heads: OC <= 16 ----------------
__global__ void __launch_bounds__(128, 4)
conv_small_kernel(const float* __restrict__ wt, const float* __restrict__ X,
                  const float* __restrict__ bias, float* __restrict__ Y,
                  int CI, int NK, int OC, int relu) {
    __shared__ float Ws[8][16];
    __shared__ float Xs[8][128];

    int y = blockIdx.x;
    int tid = threadIdx.x;
    int tx = tid & 31;
    int ty = tid >> 5;

    float acc[4][4];
#pragma unroll
    for (int i = 0; i < 4; i++)
#pragma unroll
        for (int j = 0; j < 4; j++) acc[i][j] = 0.f;

    for (int k = 0; k < NK; k++) {
        int dy = (NK == 9) ? (k / 3 - 1) : 0;
        int dx = (NK == 9) ? (k % 3 - 1) : 0;
        int yy = y + dy;
        bool rowok = (yy >= 0 && yy < Hh);

        for (int ci0 = 0; ci0 < CI; ci0 += 8) {
            {
                int kk = tid >> 4;
                int m = tid & 15;
                Ws[kk][m] = wt[((size_t)(k * CI + ci0 + kk)) * 16 + m];
            }
            {
                int kk = tid >> 4;
                int lanex = tid & 15;
                const float* xrow = X + (size_t)(ci0 + kk) * HW + yy * Ww;
#pragma unroll
                for (int j = 0; j < 8; j++) {
                    int n = lanex + 16 * j;
                    int xx = n + dx;
                    float v = 0.f;
                    if (rowok && xx >= 0 && xx < Ww) v = xrow[xx];
                    Xs[kk][n] = v;
                }
            }
            __syncthreads();
#pragma unroll
            for (int kk = 0; kk < 8; kk++) {
                float a[4], b[4];
                *(float4*)a = *(const float4*)&Ws[kk][ty * 4];
                *(float4*)b = *(const float4*)&Xs[kk][tx * 4];
#pragma unroll
                for (int i = 0; i < 4; i++)
#pragma unroll
                    for (int j = 0; j < 4; j++) acc[i][j] += a[i] * b[j];
            }
            __syncthreads();
        }
    }

#pragma unroll
    for (int i = 0; i < 4; i++) {
        int m = ty * 4 + i;
        if (m < OC) {
            float bv = bias[m];
#pragma unroll
            for (int j = 0; j < 4; j++) {
                int n = tx * 4 + j;
                float v = acc[i][j] + bv;
                if (relu) v = fmaxf(v, 0.f);
                Y[(size_t)m * HW + (size_t)y * Ww + n] = v;
            }
        }
    }
}

// ---------------- anchors + rbox decode ----------------
__global__ void decode_kernel(const float* __restrict__ bbox,
                              float* __restrict__ anchors_out,
                              float* __restrict__ refine_out) {
    int p = blockIdx.x * blockDim.x + threadIdx.x;
    if (p >= HW) return;
    int x = p & 127, yv = p >> 7;
    float ax = x * 8.f + 3.5f;
    float ay = yv * 8.f + 3.5f;
    anchors_out[p * 5 + 0] = ax;
    anchors_out[p * 5 + 1] = ay;
    anchors_out[p * 5 + 2] = 32.f;
    anchors_out[p * 5 + 3] = 32.f;
    anchors_out[p * 5 + 4] = 0.f;

    float dx = bbox[p];
    float dyv = bbox[HW + p];
    float dw = bbox[2 * HW + p];
    float dh = bbox[3 * HW + p];
    float dt = bbox[4 * HW + p];
    const float MR = 13.815510557964274f;
    dw = fminf(fmaxf(dw, -MR), MR);
    dh = fminf(fmaxf(dh, -MR), MR);
    float gx = dx * 32.f + ax;
    float gy = dyv * 32.f + ay;
    float gw = 32.f * expf(dw);
    float gh = 32.f * expf(dh);
    const float PI = 3.14159265358979323846f;
    float r = fmodf(dt + PI * 0.25f, PI);
    if (r < 0.f) r += PI;
    float ga = r - PI * 0.25f;
    refine_out[p * 5 + 0] = gx;
    refine_out[p * 5 + 1] = gy;
    refine_out[p * 5 + 2] = gw;
    refine_out[p * 5 + 3] = gh;
    refine_out[p * 5 + 4] = ga;
}

// ---------------- rotation-invariant max pooling ----------------
__global__ void maxpool8_kernel(const float* __restrict__ orf, float* __restrict__ pooled) {
    int p = blockIdx.x * blockDim.x + threadIdx.x;
    int i = blockIdx.y;
    if (p >= HW) return;
    float m = orf[(size_t)(i * 8) * HW + p];
#pragma unroll
    for (int r = 1; r < 8; r++) m = fmaxf(m, orf[(size_t)(i * 8 + r) * HW + p]);
    pooled[(size_t)i * HW + p] = m;
}

// ---------------- host orchestration ----------------
static void repack(const float* w, float* wt, int OC, int CI, int NK, int OCP) {
    int total = NK * CI * OCP;
    repack_kernel<<<(total + 255) / 256, 256>>>(w, wt, OC, CI, NK, OCP);
}

extern "C" void kernel_launch(void* const* d_in, const int* in_sizes, int n_in,
                              void* d_out, int out_size) {
    (void)in_sizes; (void)n_in; (void)out_size;

    const float* feats = (const float*)d_in[0];
    const float* fam_reg_w0 = (const float*)d_in[1];
    const float* fam_reg_b0 = (const float*)d_in[2];
    const float* fam_reg_w1 = (const float*)d_in[3];
    const float* fam_reg_b1 = (const float*)d_in[4];
    const float* fam_reg_hw = (const float*)d_in[5];
    const float* fam_reg_hb = (const float*)d_in[6];
    const float* fam_cls_w0 = (const float*)d_in[7];
    const float* fam_cls_b0 = (const float*)d_in[8];
    const float* fam_cls_w1 = (const float*)d_in[9];
    const float* fam_cls_b1 = (const float*)d_in[10];
    const float* fam_cls_hw = (const float*)d_in[11];
    const float* fam_cls_hb = (const float*)d_in[12];
    const float* align_w = (const float*)d_in[13];
    const float* align_b = (const float*)d_in[14];
    const float* or_w = (const float*)d_in[15];
    const float* or_b = (const float*)d_in[16];
    const float* odm_reg_w0 = (const float*)d_in[17];
    const float* odm_reg_b0 = (const float*)d_in[18];
    const float* odm_reg_w1 = (const float*)d_in[19];
    const float* odm_reg_b1 = (const float*)d_in[20];
    const float* odm_reg_hw = (const float*)d_in[21];
    const float* odm_reg_hb = (const float*)d_in[22];
    const float* odm_cls_w0 = (const float*)d_in[23];
    const float* odm_cls_b0 = (const float*)d_in[24];
    const float* odm_cls_w1 = (const float*)d_in[25];
    const float* odm_cls_b1 = (const float*)d_in[26];
    const float* odm_cls_hw = (const float*)d_in[27];
    const float* odm_cls_hb = (const float*)d_in[28];

    float* out = (float*)d_out;
    float* o_famcls = out;
    float* o_fambbox = out + 245760;
    float* o_odmcls = out + 327680;
    float* o_odmbbox = out + 573440;
    float* o_anchors = out + 655360;
    float* o_refine = out + 737280;

    float *b0, *b1, *b2, *pool, *wta, *wts;
    unsigned char* wp;
    __nv_bfloat16 *pah, *pal, *pbh, *pbl, *pch, *pcl;
    cudaGetSymbolAddress((void**)&b0, g_buf0);
    cudaGetSymbolAddress((void**)&b1, g_buf1);
    cudaGetSymbolAddress((void**)&b2, g_buf2);
    cudaGetSymbolAddress((void**)&pool, g_pool);
    cudaGetSymbolAddress((void**)&wta, g_wt_align);
    cudaGetSymbolAddress((void**)&wts, g_wt_small);
    cudaGetSymbolAddress((void**)&wp, g_wpack);
    cudaGetSymbolAddress((void**)&pah, g_pah);
    cudaGetSymbolAddress((void**)&pal, g_pal);
    cudaGetSymbolAddress((void**)&pbh, g_pbh);
    cudaGetSymbolAddress((void**)&pbl, g_pbl);
    cudaGetSymbolAddress((void**)&pch, g_pch);
    cudaGetSymbolAddress((void**)&pcl, g_pcl);

    cudaFuncSetAttribute(conv_hmma_kernel, cudaFuncAttributeMaxDynamicSharedMemorySize, SMEMH);

    dim3 gBig(128, 2);
    dim3 gSmall(128, 1);

    // feats -> bf16 pair (pa)
    cvt_pair_kernel<<<(CC * HW) / 256, 256>>>(feats, pah, pal, CC * HW);

    // ---- FAM reg branch ----
    repack_tc_kernel<<<2304, 256>>>(fam_reg_w0, wp, 256);
    conv_hmma_kernel<<<128, 256, SMEMH>>>(wp, pah, pal, fam_reg_b0, b0, pbh, pbl, 256, 1, 1, 0, 1);
    repack_tc_kernel<<<2304, 256>>>(fam_reg_w1, wp, 256);
    conv_hmma_kernel<<<128, 256, SMEMH>>>(wp, pbh, pbl, fam_reg_b1, b1, pbh, pbl, 256, 1, 1, 1, 0);
    repack(fam_reg_hw, wts, 5, 256, 1, 16);
    conv_small_kernel<<<gSmall, 128>>>(wts, b1, fam_reg_hb, o_fambbox, 256, 1, 5, 0);

    // ---- FAM cls branch ----
    repack_tc_kernel<<<2304, 256>>>(fam_cls_w0, wp, 256);
    conv_hmma_kernel<<<128, 256, SMEMH>>>(wp, pah, pal, fam_cls_b0, b0, pbh, pbl, 256, 1, 1, 0, 1);
    repack_tc_kernel<<<2304, 256>>>(fam_cls_w1, wp, 256);
    conv_hmma_kernel<<<128, 256, SMEMH>>>(wp, pbh, pbl, fam_cls_b1, b1, pbh, pbl, 256, 1, 1, 1, 0);
    repack(fam_cls_hw, wts, 15, 256, 1, 16);
    conv_small_kernel<<<gSmall, 128>>>(wts, b1, fam_cls_hb, o_famcls, 256, 1, 15, 0);

    // ---- anchors + decode ----
    decode_kernel<<<HW / 256, 256>>>(o_fambbox, o_anchors, o_refine);

    // ---- fused deformable align conv -> pair pa ----
    repack(align_w, wta, 256, 256, 9, 256);
    conv_align_kernel<<<gBig, 256>>>(wta, feats, o_refine, align_b, pah, pal);

    // ---- OR conv: pa -> pair pb + fp32 b0 ----
    repack_or_tc_kernel<<<2304, 256>>>(or_w, wp);
    conv_hmma_kernel<<<128, 256, SMEMH>>>(wp, pah, pal, or_b, b0, pbh, pbl, 256, 0, 8, 1, 1);

    // ---- rotation-invariant pooling + convert ----
    {
        dim3 g(HW / 256, 32);
        maxpool8_kernel<<<g, 256>>>(b0, pool);
    }
    cvt_pair_kernel<<<(32 * HW) / 256, 256>>>(pool, pch, pcl, 32 * HW);

    // ---- ODM cls branch ----
    repack_tc_kernel<<<576, 256>>>(odm_cls_w0, wp, 32);
    conv_hmma_kernel<<<128, 256, SMEMH>>>(wp, pch, pcl, odm_cls_b0, b2, pah, pal, 32, 1, 1, 0, 1);
    repack_tc_kernel<<<2304, 256>>>(odm_cls_w1, wp, 256);
    conv_hmma_kernel<<<128, 256, SMEMH>>>(wp, pah, pal, odm_cls_b1, b2, pah, pal, 256, 1, 1, 1, 0);
    repack(odm_cls_hw, wts, 15, 256, 9, 16);
    conv_small_kernel<<<gSmall, 128>>>(wts, b2, odm_cls_hb, o_odmcls, 256, 9, 15, 0);

    // ---- ODM reg branch ----
    repack_tc_kernel<<<2304, 256>>>(odm_reg_w0, wp, 256);
    conv_hmma_kernel<<<128, 256, SMEMH>>>(wp, pbh, pbl, odm_reg_b0, b1, pah, pal, 256, 1, 1, 0, 1);
    repack_tc_kernel<<<2304, 256>>>(odm_reg_w1, wp, 256);
    conv_hmma_kernel<<<128, 256, SMEMH>>>(wp, pah, pal, odm_reg_b1, b1, pah, pal, 256, 1, 1, 1, 0);
    repack(odm_reg_hw, wts, 5, 256, 9, 16);
    conv_small_kernel<<<gSmall, 128>>>(wts, b1, odm_reg_hb, o_odmbbox, 256, 9, 5, 0);
}

// round 7
// speedup vs baseline: 2.5149x; 1.4886x over previous
#include <cuda_runtime.h>
#include <cuda_bf16.h>
#include <math.h>
#include <stdint.h>

#define Hh 128
#define Ww 128
#define HW 16384
#define CC 256

// ---------------- scratch (static __device__, no allocs) ----------------
__device__ float g_b1[CC * HW];
__device__ float g_head[9 * 16 * HW];
__device__ float g_wt_small[9 * CC * 16];
__device__ unsigned char g_wpack[36 * 65536];
// pair tensors: u32 word = (bf16 ch 2m) | (bf16 ch 2m+1 << 16), index m*HW + p
__device__ uint32_t g_p0h[128 * HW];
__device__ uint32_t g_p0l[128 * HW];
__device__ uint32_t g_p1h[128 * HW];
__device__ uint32_t g_p1l[128 * HW];
__device__ uint32_t g_p2h[128 * HW];
__device__ uint32_t g_p2l[128 * HW];
__device__ uint32_t g_pdh[16 * HW];
__device__ uint32_t g_pdl[16 * HW];

__constant__ int c_ring[8] = {0, 1, 2, 5, 8, 7, 6, 3};

// ---------------- helpers ----------------
__device__ __forceinline__ uint32_t smem_u32(const void* p) {
    uint32_t a;
    asm("{ .reg .u64 t; cvta.to.shared.u64 t, %1; cvt.u32.u64 %0, t; }" : "=r"(a) : "l"(p));
    return a;
}
__device__ __forceinline__ void ldm4(uint32_t* r, uint32_t addr) {
    asm volatile("ldmatrix.sync.aligned.m8n8.x4.shared.b16 {%0,%1,%2,%3}, [%4];"
                 : "=r"(r[0]), "=r"(r[1]), "=r"(r[2]), "=r"(r[3]) : "r"(addr));
}
__device__ __forceinline__ void mma_bf16(float* c, const uint32_t* a, uint32_t b0, uint32_t b1) {
    asm volatile(
        "mma.sync.aligned.m16n8k16.row.col.f32.bf16.bf16.f32 "
        "{%0,%1,%2,%3}, {%4,%5,%6,%7}, {%8,%9}, {%0,%1,%2,%3};"
        : "+f"(c[0]), "+f"(c[1]), "+f"(c[2]), "+f"(c[3])
        : "r"(a[0]), "r"(a[1]), "r"(a[2]), "r"(a[3]), "r"(b0), "r"(b1));
}
__device__ __forceinline__ unsigned short bf16u(float v) {
    __nv_bfloat16 b = __float2bfloat16(v);
    return *(unsigned short*)&b;
}
__device__ __forceinline__ float ubf(unsigned short u) {
    __nv_bfloat16 b = *(__nv_bfloat16*)&u;
    return __bfloat162float(b);
}
__device__ __forceinline__ float half_of(uint32_t w, int hi) {
    return ubf((unsigned short)(hi ? (w >> 16) : (w & 0xFFFF)));
}
__device__ __forceinline__ void cp_async_tile(uint32_t dst, const unsigned char* src, int tid) {
#pragma unroll
    for (int i = 0; i < 16; i++) {
        asm volatile("cp.async.cg.shared.global [%0], [%1], 16;"
                     :: "r"(dst + (uint32_t)(tid + i * 256) * 16),
                        "l"(src + (size_t)(tid + i * 256) * 16) : "memory");
    }
    asm volatile("cp.async.commit_group;" ::: "memory");
}
__device__ __forceinline__ void cp_async_wait0() {
    asm volatile("cp.async.wait_group 0;" ::: "memory");
}

// ---------------- weight repack to packed bf16 hi/lo SW128 tiles ----------------
__global__ void repack_tc_kernel(const float* __restrict__ w,
                                 unsigned char* __restrict__ wp, int CI) {
    int ncc = (CI + 63) >> 6;
    int total = 9 * ncc * 16384;
    int idx = blockIdx.x * blockDim.x + threadIdx.x;
    if (idx >= total) return;
    int kc = idx & 63;
    int oc = (idx >> 6) & 255;
    int sub = idx >> 14;
    int tap = sub / ncc, cc2 = sub % ncc;
    int ci = (cc2 << 6) + kc;
    float v = (ci < CI) ? w[((size_t)oc * CI + ci) * 9 + tap] : 0.f;
    __nv_bfloat16 hb = __float2bfloat16(v);
    __nv_bfloat16 lb = __float2bfloat16(v - __bfloat162float(hb));
    int half = oc >> 7, ocl = oc & 127;
    uint32_t ofs = (uint32_t)ocl * 128u + (((uint32_t)kc * 2u) ^ (((uint32_t)ocl & 7u) << 4));
    size_t base = (size_t)sub * 65536 + (size_t)(half * 2) * 16384;
    *(unsigned short*)(wp + base + ofs) = *(unsigned short*)&hb;
    *(unsigned short*)(wp + base + 16384 + ofs) = *(unsigned short*)&lb;
}

__global__ void repack_or_tc_kernel(const float* __restrict__ w,
                                    unsigned char* __restrict__ wp) {
    int idx = blockIdx.x * blockDim.x + threadIdx.x;
    if (idx >= 36 * 16384) return;
    int kc = idx & 63;
    int oc = (idx >> 6) & 255;
    int sub = idx >> 14;
    int tap = sub >> 2, cc2 = sub & 3;
    int ci = (cc2 << 6) + kc;
    int o = oc >> 3, r = oc & 7;
    int s;
    if (tap == 4) {
        s = 4;
    } else {
        int j = 0;
#pragma unroll
        for (int t = 0; t < 8; t++)
            if (c_ring[t] == tap) j = t;
        s = c_ring[(j - r + 8) & 7];
    }
    float v = w[((size_t)o * CC + ci) * 9 + s];
    __nv_bfloat16 hb = __float2bfloat16(v);
    __nv_bfloat16 lb = __float2bfloat16(v - __bfloat162float(hb));
    int half = oc >> 7, ocl = oc & 127;
    uint32_t ofs = (uint32_t)ocl * 128u + (((uint32_t)kc * 2u) ^ (((uint32_t)ocl & 7u) << 4));
    size_t base = (size_t)sub * 65536 + (size_t)(half * 2) * 16384;
    *(unsigned short*)(wp + base + ofs) = *(unsigned short*)&hb;
    *(unsigned short*)(wp + base + 16384 + ofs) = *(unsigned short*)&lb;
}

// ---------------- fp32 [C][HW] -> pair-interleaved u32 words ----------------
__global__ void cvt_pair_kernel(const float* __restrict__ x,
                                uint32_t* __restrict__ h, uint32_t* __restrict__ l,
                                int nwords) {
    int i = blockIdx.x * blockDim.x + threadIdx.x;
    if (i >= nwords) return;
    int cp = i >> 14, p = i & 16383;
    float v0 = x[(size_t)(cp * 2) * HW + p];
    float v1 = x[(size_t)(cp * 2 + 1) * HW + p];
    unsigned short h0 = bf16u(v0), h1 = bf16u(v1);
    float l0f = v0 - ubf(h0), l1f = v1 - ubf(h1);
    h[i] = (uint32_t)h0 | ((uint32_t)h1 << 16);
    l[i] = (uint32_t)bf16u(l0f) | ((uint32_t)bf16u(l1f) << 16);
}

// ---------------- shared MMA core pieces ----------------
__device__ __forceinline__ void mma_substage(uint32_t aA, uint32_t aB, int half,
                                             int mrow0, int nbase, int lrow, int lcol16,
                                             float acc[4][8][4]) {
#pragma unroll
    for (int ks = 0; ks < 4; ks++) {
        int kb = ks * 32;
        uint32_t Ah[4][4], Al[4][4];
#pragma unroll
        for (int mt = 0; mt < 4; mt++) {
            int row = mrow0 + mt * 16 + lrow;
            uint32_t roff = (uint32_t)row * 128u +
                            (((uint32_t)(kb + lcol16)) ^ (((uint32_t)row & 7u) << 4));
            ldm4(Ah[mt], aA + (half * 2 + 0) * 16384 + roff);
            ldm4(Al[mt], aA + (half * 2 + 1) * 16384 + roff);
        }
        {
            uint32_t Bh[4][4];
#pragma unroll
            for (int nt = 0; nt < 4; nt++) {
                int row = nbase + nt * 16 + lrow;
                uint32_t roff = (uint32_t)row * 128u +
                                (((uint32_t)(kb + lcol16)) ^ (((uint32_t)row & 7u) << 4));
                ldm4(Bh[nt], aB + roff);
            }
#pragma unroll
            for (int mt = 0; mt < 4; mt++)
#pragma unroll
                for (int nt = 0; nt < 4; nt++) {
                    mma_bf16(acc[mt][nt * 2 + 0], Ah[mt], Bh[nt][0], Bh[nt][2]);
                    mma_bf16(acc[mt][nt * 2 + 0], Al[mt], Bh[nt][0], Bh[nt][2]);
                    mma_bf16(acc[mt][nt * 2 + 1], Ah[mt], Bh[nt][1], Bh[nt][3]);
                    mma_bf16(acc[mt][nt * 2 + 1], Al[mt], Bh[nt][1], Bh[nt][3]);
                }
        }
        {
            uint32_t Bl[4][4];
#pragma unroll
            for (int nt = 0; nt < 4; nt++) {
                int row = nbase + nt * 16 + lrow;
                uint32_t roff = (uint32_t)row * 128u +
                                (((uint32_t)(kb + lcol16)) ^ (((uint32_t)row & 7u) << 4));
                ldm4(Bl[nt], aB + 16384 + roff);
            }
#pragma unroll
            for (int mt = 0; mt < 4; mt++)
#pragma unroll
                for (int nt = 0; nt < 4; nt++) {
                    mma_bf16(acc[mt][nt * 2 + 0], Ah[mt], Bl[nt][0], Bl[nt][2]);
                    mma_bf16(acc[mt][nt * 2 + 1], Ah[mt], Bl[nt][1], Bl[nt][3]);
                }
        }
    }
}

__device__ __forceinline__ void mma_epilogue(float acc[4][8][4], int mbase, int nbase,
                                             int lane, int y, const float* bias,
                                             int relu, int bias_div, int writeF, int writeP,
                                             float* Yf, unsigned short* Yh,
                                             unsigned short* Yl) {
    int qr = lane >> 2, qc = lane & 3;
#pragma unroll
    for (int mt = 0; mt < 4; mt++) {
#pragma unroll
        for (int nf = 0; nf < 8; nf++) {
#pragma unroll
            for (int p = 0; p < 2; p++) {
                int oc = mbase + mt * 16 + qr + p * 8;
                int pxo = nbase + nf * 8 + qc * 2;
                float bv = bias[oc / bias_div];
                float v0 = acc[mt][nf][p * 2 + 0] + bv;
                float v1 = acc[mt][nf][p * 2 + 1] + bv;
                if (relu) { v0 = fmaxf(v0, 0.f); v1 = fmaxf(v1, 0.f); }
                if (writeF) {
                    *(float2*)(Yf + (size_t)oc * HW + (size_t)y * Ww + pxo) =
                        make_float2(v0, v1);
                }
                if (writeP) {
                    size_t w0 = (size_t)(oc >> 1) * HW + (size_t)y * Ww + pxo;
                    int hb = oc & 1;
                    unsigned short h0 = bf16u(v0), h1 = bf16u(v1);
                    Yh[w0 * 2 + hb] = h0;
                    Yh[(w0 + 1) * 2 + hb] = h1;
                    Yl[w0 * 2 + hb] = bf16u(v0 - ubf(h0));
                    Yl[(w0 + 1) * 2 + hb] = bf16u(v1 - ubf(h1));
                }
            }
        }
    }
}

// ---------------- HMMA conv (direct im2col from pair tensors) ----------------
#define SMEMH 163840
__global__ void __launch_bounds__(256, 1)
conv_hmma_kernel(const unsigned char* __restrict__ wpack,
                 const uint32_t* __restrict__ Xh, const uint32_t* __restrict__ Xl,
                 const float* __restrict__ bias, float* __restrict__ Yf,
                 unsigned short* __restrict__ Yh, unsigned short* __restrict__ Yl,
                 int CI, int relu, int bias_div, int writeF, int writeP) {
    extern __shared__ unsigned char sm[];
    uint32_t aSm = smem_u32(sm);
    uint32_t aB = aSm + 131072;

    int tid = threadIdx.x;
    int y = blockIdx.x;
    int lane = tid & 31, wid = tid >> 5;
    int wm = wid >> 1, wn = wid & 1;
    int mbase = wm * 64;
    int half = mbase >> 7;
    int mrow0 = mbase & 127;
    int nbase = wn * 64;
    int lrow = (lane & 7) + ((lane >> 3) & 1) * 8;
    int lcol16 = (lane >> 4) * 16;
    int role = tid >> 7;
    int px = tid & 127;
    int ncc = (CI + 63) >> 6;
    int nsub = 9 * ncc;

    float acc[4][8][4];
#pragma unroll
    for (int a = 0; a < 4; a++)
#pragma unroll
        for (int b = 0; b < 8; b++)
#pragma unroll
            for (int c = 0; c < 4; c++) acc[a][b][c] = 0.f;

    cp_async_tile(aSm, wpack, tid);  // A[0]

    const uint32_t* Xrole = role ? Xl : Xh;

    for (int sub = 0; sub < nsub; sub++) {
        int tap = sub / ncc;
        int ci0 = (sub - tap * ncc) << 6;
        int dy = tap / 3 - 1, dx = tap % 3 - 1;
        int ysrc = y + dy, xsrc = px + dx;
        bool ok = (ysrc >= 0) && (ysrc < Hh) && (xsrc >= 0) && (xsrc < Ww);
        int poff = ysrc * Ww + xsrc;
        int prb = ci0 >> 1;
        // build B tile (role picks hi or lo tensor)
#pragma unroll
        for (int g = 0; g < 8; g++) {
            uint32_t pk[4];
#pragma unroll
            for (int q = 0; q < 4; q++) {
                int ci = ci0 + (g * 4 + q) * 2;
                uint32_t v = 0;
                if (ok && ci < CI) v = Xrole[(size_t)(prb + g * 4 + q) * HW + poff];
                pk[q] = v;
            }
            uint32_t ofs = (uint32_t)px * 128u +
                           (((uint32_t)g << 4) ^ (((uint32_t)px & 7u) << 4));
            *(uint4*)(sm + 131072 + role * 16384 + ofs) = make_uint4(pk[0], pk[1], pk[2], pk[3]);
        }
        cp_async_wait0();
        __syncthreads();
        if (sub + 1 < nsub)
            cp_async_tile(aSm + ((sub + 1) & 1) * 65536, wpack + (size_t)(sub + 1) * 65536, tid);
        mma_substage(aSm + (sub & 1) * 65536, aB, half, mrow0, nbase, lrow, lcol16, acc);
        __syncthreads();
    }

    mma_epilogue(acc, mbase, nbase, lane, y, bias, relu, bias_div, writeF, writeP,
                 Yf, Yh, Yl);
}

// ---------------- deformable HMMA conv (bilinear-sampled B from fp32 feats) ------
#define SMEMD 200704
__global__ void __launch_bounds__(256, 1)
conv_deform_kernel(const unsigned char* __restrict__ wpack,
                   const float* __restrict__ feats, const float* __restrict__ refine,
                   const float* __restrict__ bias,
                   unsigned short* __restrict__ Yh, unsigned short* __restrict__ Yl) {
    extern __shared__ unsigned char sm[];
    uint32_t aSm = smem_u32(sm);
    uint32_t aB = aSm + 131072;
    int* s_idx = (int*)(sm + 163840);
    float* s_wt = (float*)(sm + 163840 + 18432);

    int tid = threadIdx.x;
    int y = blockIdx.x;
    int lane = tid & 31, wid = tid >> 5;
    int wm = wid >> 1, wn = wid & 1;
    int mbase = wm * 64;
    int half = mbase >> 7;
    int mrow0 = mbase & 127;
    int nbase = wn * 64;
    int lrow = (lane & 7) + ((lane >> 3) & 1) * 8;
    int lcol16 = (lane >> 4) * 16;
    int role = tid >> 7;
    int px = tid & 127;

    // bilinear tables for this row
    for (int e = tid; e < 128 * 9; e += 256) {
        int pxe = e / 9, k = e % 9;
        int p = y * Ww + pxe;
        float axc = refine[p * 5 + 0] * 0.125f;
        float ayc = refine[p * 5 + 1] * 0.125f;
        float aw = refine[p * 5 + 2] * 0.125f;
        float ah = refine[p * 5 + 3] * 0.125f;
        float aa = refine[p * 5 + 4];
        float cs = cosf(aa), sn = sinf(aa);
        float kx = (float)(k % 3 - 1);
        float ky = (float)(k / 3 - 1);
        float ddx = (aw * (1.f / 3.f)) * kx;
        float ddy = (ah * (1.f / 3.f)) * ky;
        float xs = cs * ddx - sn * ddy + axc;
        float ys = sn * ddx + cs * ddy + ayc;
        float x0f = floorf(xs), y0f = floorf(ys);
        float wx1 = xs - x0f, wx0 = 1.f - wx1;
        float wy1 = ys - y0f, wy0 = 1.f - wy1;
        int x0 = (int)x0f, y0 = (int)y0f;
#pragma unroll
        for (int c = 0; c < 4; c++) {
            int xi = x0 + (c & 1);
            int yi = y0 + (c >> 1);
            float ww = ((c & 1) ? wx1 : wx0) * ((c >> 1) ? wy1 : wy0);
            bool valid = (xi >= 0 && xi < Ww && yi >= 0 && yi < Hh);
            int xc = min(max(xi, 0), Ww - 1);
            int yc = min(max(yi, 0), Hh - 1);
            s_idx[(k * 4 + c) * 128 + pxe] = yc * Ww + xc;
            s_wt[(k * 4 + c) * 128 + pxe] = valid ? ww : 0.f;
        }
    }

    float acc[4][8][4];
#pragma unroll
    for (int a = 0; a < 4; a++)
#pragma unroll
        for (int b = 0; b < 8; b++)
#pragma unroll
            for (int c = 0; c < 4; c++) acc[a][b][c] = 0.f;

    cp_async_tile(aSm, wpack, tid);
    __syncthreads();  // tables visible

    for (int sub = 0; sub < 36; sub++) {
        int tap = sub >> 2;
        int ci0 = (sub & 3) << 6;
        int I0 = s_idx[(tap * 4 + 0) * 128 + px];
        int I1 = s_idx[(tap * 4 + 1) * 128 + px];
        int I2 = s_idx[(tap * 4 + 2) * 128 + px];
        int I3 = s_idx[(tap * 4 + 3) * 128 + px];
        float W0 = s_wt[(tap * 4 + 0) * 128 + px];
        float W1 = s_wt[(tap * 4 + 1) * 128 + px];
        float W2 = s_wt[(tap * 4 + 2) * 128 + px];
        float W3 = s_wt[(tap * 4 + 3) * 128 + px];
        int cbase = ci0 + role * 32;
        uint32_t hv[16], lv[16];
#pragma unroll
        for (int j = 0; j < 16; j++) {
            const float* f0 = feats + (size_t)(cbase + j * 2) * HW;
            const float* f1 = feats + (size_t)(cbase + j * 2 + 1) * HW;
            float v0 = f0[I0] * W0 + f0[I1] * W1 + f0[I2] * W2 + f0[I3] * W3;
            float v1 = f1[I0] * W0 + f1[I1] * W1 + f1[I2] * W2 + f1[I3] * W3;
            unsigned short h0 = bf16u(v0), h1 = bf16u(v1);
            hv[j] = (uint32_t)h0 | ((uint32_t)h1 << 16);
            lv[j] = (uint32_t)bf16u(v0 - ubf(h0)) | ((uint32_t)bf16u(v1 - ubf(h1)) << 16);
        }
#pragma unroll
        for (int gg = 0; gg < 4; gg++) {
            int g = role * 4 + gg;
            uint32_t ofs = (uint32_t)px * 128u +
                           (((uint32_t)g << 4) ^ (((uint32_t)px & 7u) << 4));
            *(uint4*)(sm + 131072 + ofs) = *(uint4*)&hv[gg * 4];
            *(uint4*)(sm + 131072 + 16384 + ofs) = *(uint4*)&lv[gg * 4];
        }
        cp_async_wait0();
        __syncthreads();
        if (sub + 1 < 36)
            cp_async_tile(aSm + ((sub + 1) & 1) * 65536, wpack + (size_t)(sub + 1) * 65536, tid);
        mma_substage(aSm + (sub & 1) * 65536, aB, half, mrow0, nbase, lrow, lcol16, acc);
        __syncthreads();
    }

    mma_epilogue(acc, mbase, nbase, lane, y, bias, 1, 1, 0, 1, (float*)0, Yh, Yl);
}

// ---------------- head partial conv (one 3x3 tap per block) ----------------
__global__ void __launch_bounds__(128, 4)
head_part_kernel(const float* __restrict__ wt, const float* __restrict__ X,
                 float* __restrict__ part, int CI, int NK) {
    __shared__ float Ws[8][16];
    __shared__ float Xs[8][128];

    int y = blockIdx.x;
    int k = blockIdx.y;
    int tid = threadIdx.x;
    int tx = tid & 31;
    int ty = tid >> 5;

    float acc[4][4];
#pragma unroll
    for (int i = 0; i < 4; i++)
#pragma unroll
        for (int j = 0; j < 4; j++) acc[i][j] = 0.f;

    int dy = (NK == 9) ? (k / 3 - 1) : 0;
    int dx = (NK == 9) ? (k % 3 - 1) : 0;
    int yy = y + dy;
    bool rowok = (yy >= 0 && yy < Hh);

    for (int ci0 = 0; ci0 < CI; ci0 += 8) {
        {
            int kk = tid >> 4;
            int m = tid & 15;
            Ws[kk][m] = wt[((size_t)(k * CI + ci0 + kk)) * 16 + m];
        }
        {
            int kk = tid >> 4;
            int lanex = tid & 15;
            const float* xrow = X + (size_t)(ci0 + kk) * HW + yy * Ww;
#pragma unroll
            for (int j = 0; j < 8; j++) {
                int n = lanex + 16 * j;
                int xx = n + dx;
                float v = 0.f;
                if (rowok && xx >= 0 && xx < Ww) v = xrow[xx];
                Xs[kk][n] = v;
            }
        }
        __syncthreads();
#pragma unroll
        for (int kk = 0; kk < 8; kk++) {
            float a[4], b[4];
            *(float4*)a = *(const float4*)&Ws[kk][ty * 4];
            *(float4*)b = *(const float4*)&Xs[kk][tx * 4];
#pragma unroll
            for (int i = 0; i < 4; i++)
#pragma unroll
                for (int j = 0; j < 4; j++) acc[i][j] += a[i] * b[j];
        }
        __syncthreads();
    }

#pragma unroll
    for (int i = 0; i < 4; i++) {
        int m = ty * 4 + i;
#pragma unroll
        for (int j = 0; j < 4; j++) {
            int n = tx * 4 + j;
            part[((size_t)k * 16 + m) * HW + (size_t)y * Ww + n] = acc[i][j];
        }
    }
}

__global__ void head_reduce_kernel(const float* __restrict__ part,
                                   const float* __restrict__ bias,
                                   float* __restrict__ Y, int OC, int NK) {
    int idx = blockIdx.x * blockDim.x + threadIdx.x;
    if (idx >= OC * HW) return;
    int m = idx / HW, p = idx - m * HW;
    float s = bias[m];
    for (int t = 0; t < NK; t++) s += part[((size_t)t * 16 + m) * HW + p];
    Y[(size_t)m * HW + p] = s;
}

// ---------------- anchors + rbox decode ----------------
__global__ void decode_kernel(const float* __restrict__ bbox,
                              float* __restrict__ anchors_out,
                              float* __restrict__ refine_out) {
    int p = blockIdx.x * blockDim.x + threadIdx.x;
    if (p >= HW) return;
    int x = p & 127, yv = p >> 7;
    float ax = x * 8.f + 3.5f;
    float ay = yv * 8.f + 3.5f;
    anchors_out[p * 5 + 0] = ax;
    anchors_out[p * 5 + 1] = ay;
    anchors_out[p * 5 + 2] = 32.f;
    anchors_out[p * 5 + 3] = 32.f;
    anchors_out[p * 5 + 4] = 0.f;

    float dx = bbox[p];
    float dyv = bbox[HW + p];
    float dw = bbox[2 * HW + p];
    float dh = bbox[3 * HW + p];
    float dt = bbox[4 * HW + p];
    const float MR = 13.815510557964274f;
    dw = fminf(fmaxf(dw, -MR), MR);
    dh = fminf(fmaxf(dh, -MR), MR);
    float gx = dx * 32.f + ax;
    float gy = dyv * 32.f + ay;
    float gw = 32.f * expf(dw);
    float gh = 32.f * expf(dh);
    const float PI = 3.14159265358979323846f;
    float r = fmodf(dt + PI * 0.25f, PI);
    if (r < 0.f) r += PI;
    float ga = r - PI * 0.25f;
    refine_out[p * 5 + 0] = gx;
    refine_out[p * 5 + 1] = gy;
    refine_out[p * 5 + 2] = gw;
    refine_out[p * 5 + 3] = gh;
    refine_out[p * 5 + 4] = ga;
}

// ---------------- rotation-invariant max pooling on pair tensors ----------------
__global__ void maxpool8_kernel(const uint32_t* __restrict__ oh,
                                const uint32_t* __restrict__ ol,
                                unsigned short* __restrict__ ph,
                                unsigned short* __restrict__ pl) {
    int p = blockIdx.x * blockDim.x + threadIdx.x;
    int i = blockIdx.y;
    if (p >= HW) return;
    float m = -1e30f;
#pragma unroll
    for (int r2 = 0; r2 < 4; r2++) {
        size_t w = (size_t)(i * 4 + r2) * HW + p;
        uint32_t wh = oh[w], wl = ol[w];
        float v0 = half_of(wh, 0) + half_of(wl, 0);
        float v1 = half_of(wh, 1) + half_of(wl, 1);
        m = fmaxf(m, fmaxf(v0, v1));
    }
    size_t wo = ((size_t)(i >> 1) * HW + p) * 2 + (i & 1);
    unsigned short hb = bf16u(m);
    ph[wo] = hb;
    pl[wo] = bf16u(m - ubf(hb));
}

// ---------------- generic float repack (head weights) ----------------
__global__ void repack_kernel(const float* __restrict__ w, float* __restrict__ wt,
                              int OC, int CI, int NK, int OCP) {
    int idx = blockIdx.x * blockDim.x + threadIdx.x;
    int total = NK * CI * OCP;
    if (idx >= total) return;
    int oc = idx % OCP;
    int ci = (idx / OCP) % CI;
    int k = idx / (OCP * CI);
    wt[idx] = (oc < OC) ? w[((size_t)oc * CI + ci) * NK + k] : 0.f;
}

// ---------------- host orchestration ----------------
static void repack(const float* w, float* wt, int OC, int CI, int NK, int OCP) {
    int total = NK * CI * OCP;
    repack_kernel<<<(total + 255) / 256, 256>>>(w, wt, OC, CI, NK, OCP);
}

extern "C" void kernel_launch(void* const* d_in, const int* in_sizes, int n_in,
                              void* d_out, int out_size) {
    (void)in_sizes; (void)n_in; (void)out_size;

    const float* feats = (const float*)d_in[0];
    const float* fam_reg_w0 = (const float*)d_in[1];
    const float* fam_reg_b0 = (const float*)d_in[2];
    const float* fam_reg_w1 = (const float*)d_in[3];
    const float* fam_reg_b1 = (const float*)d_in[4];
    const float* fam_reg_hw = (const float*)d_in[5];
    const float* fam_reg_hb = (const float*)d_in[6];
    const float* fam_cls_w0 = (const float*)d_in[7];
    const float* fam_cls_b0 = (const float*)d_in[8];
    const float* fam_cls_w1 = (const float*)d_in[9];
    const float* fam_cls_b1 = (const float*)d_in[10];
    const float* fam_cls_hw = (const float*)d_in[11];
    const float* fam_cls_hb = (const float*)d_in[12];
    const float* align_w = (const float*)d_in[13];
    const float* align_b = (const float*)d_in[14];
    const float* or_w = (const float*)d_in[15];
    const float* or_b = (const float*)d_in[16];
    const float* odm_reg_w0 = (const float*)d_in[17];
    const float* odm_reg_b0 = (const float*)d_in[18];
    const float* odm_reg_w1 = (const float*)d_in[19];
    const float* odm_reg_b1 = (const float*)d_in[20];
    const float* odm_reg_hw = (const float*)d_in[21];
    const float* odm_reg_hb = (const float*)d_in[22];
    const float* odm_cls_w0 = (const float*)d_in[23];
    const float* odm_cls_b0 = (const float*)d_in[24];
    const float* odm_cls_w1 = (const float*)d_in[25];
    const float* odm_cls_b1 = (const float*)d_in[26];
    const float* odm_cls_hw = (const float*)d_in[27];
    const float* odm_cls_hb = (const float*)d_in[28];

    float* out = (float*)d_out;
    float* o_famcls = out;
    float* o_fambbox = out + 245760;
    float* o_odmcls = out + 327680;
    float* o_odmbbox = out + 573440;
    float* o_anchors = out + 655360;
    float* o_refine = out + 737280;

    float *b1, *wts, *hd;
    unsigned char* wp;
    uint32_t *p0h, *p0l, *p1h, *p1l, *p2h, *p2l, *pdh, *pdl;
    cudaGetSymbolAddress((void**)&b1, g_b1);
    cudaGetSymbolAddress((void**)&hd, g_head);
    cudaGetSymbolAddress((void**)&wts, g_wt_small);
    cudaGetSymbolAddress((void**)&wp, g_wpack);
    cudaGetSymbolAddress((void**)&p0h, g_p0h);
    cudaGetSymbolAddress((void**)&p0l, g_p0l);
    cudaGetSymbolAddress((void**)&p1h, g_p1h);
    cudaGetSymbolAddress((void**)&p1l, g_p1l);
    cudaGetSymbolAddress((void**)&p2h, g_p2h);
    cudaGetSymbolAddress((void**)&p2l, g_p2l);
    cudaGetSymbolAddress((void**)&pdh, g_pdh);
    cudaGetSymbolAddress((void**)&pdl, g_pdl);

    cudaFuncSetAttribute(conv_hmma_kernel, cudaFuncAttributeMaxDynamicSharedMemorySize, SMEMH);
    cudaFuncSetAttribute(conv_deform_kernel, cudaFuncAttributeMaxDynamicSharedMemorySize, SMEMD);

    // feats -> pair P0
    cvt_pair_kernel<<<8192, 256>>>(feats, p0h, p0l, 128 * HW);

    // ---- FAM reg branch ----
    repack_tc_kernel<<<2304, 256>>>(fam_reg_w0, wp, 256);
    conv_hmma_kernel<<<128, 256, SMEMH>>>(wp, p0h, p0l, fam_reg_b0, b1,
                                          (unsigned short*)p1h, (unsigned short*)p1l,
                                          256, 1, 1, 0, 1);
    repack_tc_kernel<<<2304, 256>>>(fam_reg_w1, wp, 256);
    conv_hmma_kernel<<<128, 256, SMEMH>>>(wp, p1h, p1l, fam_reg_b1, b1,
                                          (unsigned short*)p2h, (unsigned short*)p2l,
                                          256, 1, 1, 1, 0);
    repack(fam_reg_hw, wts, 5, 256, 1, 16);
    head_part_kernel<<<dim3(128, 1), 128>>>(wts, b1, hd, 256, 1);
    head_reduce_kernel<<<(5 * HW + 255) / 256, 256>>>(hd, fam_reg_hb, o_fambbox, 5, 1);

    // ---- FAM cls branch ----
    repack_tc_kernel<<<2304, 256>>>(fam_cls_w0, wp, 256);
    conv_hmma_kernel<<<128, 256, SMEMH>>>(wp, p0h, p0l, fam_cls_b0, b1,
                                          (unsigned short*)p1h, (unsigned short*)p1l,
                                          256, 1, 1, 0, 1);
    repack_tc_kernel<<<2304, 256>>>(fam_cls_w1, wp, 256);
    conv_hmma_kernel<<<128, 256, SMEMH>>>(wp, p1h, p1l, fam_cls_b1, b1,
                                          (unsigned short*)p2h, (unsigned short*)p2l,
                                          256, 1, 1, 1, 0);
    repack(fam_cls_hw, wts, 15, 256, 1, 16);
    head_part_kernel<<<dim3(128, 1), 128>>>(wts, b1, hd, 256, 1);
    head_reduce_kernel<<<(15 * HW + 255) / 256, 256>>>(hd, fam_cls_hb, o_famcls, 15, 1);

    // ---- anchors + decode ----
    decode_kernel<<<HW / 256, 256>>>(o_fambbox, o_anchors, o_refine);

    // ---- deformable align conv: feats -> P1 pair ----
    repack_tc_kernel<<<2304, 256>>>(align_w, wp, 256);
    conv_deform_kernel<<<128, 256, SMEMD>>>(wp, feats, o_refine, align_b,
                                            (unsigned short*)p1h, (unsigned short*)p1l);

    // ---- OR conv: P1 -> P2 pair ----
    repack_or_tc_kernel<<<2304, 256>>>(or_w, wp);
    conv_hmma_kernel<<<128, 256, SMEMH>>>(wp, p1h, p1l, or_b, b1,
                                          (unsigned short*)p2h, (unsigned short*)p2l,
                                          256, 0, 8, 0, 1);

    // ---- rotation-invariant pooling: P2 -> PD pair ----
    {
        dim3 g(HW / 256, 32);
        maxpool8_kernel<<<g, 256>>>(p2h, p2l, (unsigned short*)pdh, (unsigned short*)pdl);
    }

    // ---- ODM cls branch ----
    repack_tc_kernel<<<576, 256>>>(odm_cls_w0, wp, 32);
    conv_hmma_kernel<<<128, 256, SMEMH>>>(wp, pdh, pdl, odm_cls_b0, b1,
                                          (unsigned short*)p0h, (unsigned short*)p0l,
                                          32, 1, 1, 0, 1);
    repack_tc_kernel<<<2304, 256>>>(odm_cls_w1, wp, 256);
    conv_hmma_kernel<<<128, 256, SMEMH>>>(wp, p0h, p0l, odm_cls_b1, b1,
                                          (unsigned short*)p1h, (unsigned short*)p1l,
                                          256, 1, 1, 1, 0);
    repack(odm_cls_hw, wts, 15, 256, 9, 16);
    head_part_kernel<<<dim3(128, 9), 128>>>(wts, b1, hd, 256, 9);
    head_reduce_kernel<<<(15 * HW + 255) / 256, 256>>>(hd, odm_cls_hb, o_odmcls, 15, 9);

    // ---- ODM reg branch ----
    repack_tc_kernel<<<2304, 256>>>(odm_reg_w0, wp, 256);
    conv_hmma_kernel<<<128, 256, SMEMH>>>(wp, p2h, p2l, odm_reg_b0, b1,
                                          (unsigned short*)p0h, (unsigned short*)p0l,
                                          256, 1, 1, 0, 1);
    repack_tc_kernel<<<2304, 256>>>(odm_reg_w1, wp, 256);
    conv_hmma_kernel<<<128, 256, SMEMH>>>(wp, p0h, p0l, odm_reg_b1, b1,
                                          (unsigned short*)p1h, (unsigned short*)p1l,
                                          256, 1, 1, 1, 0);
    repack(odm_reg_hw, wts, 5, 256, 9, 16);
    head_part_kernel<<<dim3(128, 9), 128>>>(wts, b1, hd, 256, 9);
    head_reduce_kernel<<<(5 * HW + 255) / 256, 256>>>(hd, odm_reg_hb, o_odmbbox, 5, 9);
}

// round 8
// speedup vs baseline: 2.5740x; 1.0235x over previous
#include <cuda_runtime.h>
#include <cuda_bf16.h>
#include <math.h>
#include <stdint.h>

#define Hh 128
#define Ww 128
#define HW 16384
#define CC 256

// ---------------- scratch (static __device__, no allocs) ----------------
__device__ float g_b1[CC * HW];
__device__ float g_b2[CC * HW];
__device__ float g_head[9 * 16 * HW];
__device__ float g_wt_small[81920];
__device__ unsigned char g_wpack[333 * 65536];
// pair tensors: u32 word = (bf16 ch 2m) | (bf16 ch 2m+1 << 16), index m*HW + p
__device__ uint32_t g_p0h[128 * HW];
__device__ uint32_t g_p0l[128 * HW];
__device__ uint32_t g_p1h[128 * HW];
__device__ uint32_t g_p1l[128 * HW];
__device__ uint32_t g_p2h[128 * HW];
__device__ uint32_t g_p2l[128 * HW];
__device__ uint32_t g_p3h[128 * HW];
__device__ uint32_t g_p3l[128 * HW];
__device__ uint32_t g_pdh[16 * HW];
__device__ uint32_t g_pdl[16 * HW];

__constant__ int c_ring[8] = {0, 1, 2, 5, 8, 7, 6, 3};

struct WPtrs {
    const float* w[9];
};

// ---------------- helpers ----------------
__device__ __forceinline__ uint32_t smem_u32(const void* p) {
    uint32_t a;
    asm("{ .reg .u64 t; cvta.to.shared.u64 t, %1; cvt.u32.u64 %0, t; }" : "=r"(a) : "l"(p));
    return a;
}
__device__ __forceinline__ void ldm4(uint32_t* r, uint32_t addr) {
    asm volatile("ldmatrix.sync.aligned.m8n8.x4.shared.b16 {%0,%1,%2,%3}, [%4];"
                 : "=r"(r[0]), "=r"(r[1]), "=r"(r[2]), "=r"(r[3]) : "r"(addr));
}
__device__ __forceinline__ void mma_bf16(float* c, const uint32_t* a, uint32_t b0, uint32_t b1) {
    asm volatile(
        "mma.sync.aligned.m16n8k16.row.col.f32.bf16.bf16.f32 "
        "{%0,%1,%2,%3}, {%4,%5,%6,%7}, {%8,%9}, {%0,%1,%2,%3};"
        : "+f"(c[0]), "+f"(c[1]), "+f"(c[2]), "+f"(c[3])
        : "r"(a[0]), "r"(a[1]), "r"(a[2]), "r"(a[3]), "r"(b0), "r"(b1));
}
__device__ __forceinline__ unsigned short bf16u(float v) {
    __nv_bfloat16 b = __float2bfloat16(v);
    return *(unsigned short*)&b;
}
__device__ __forceinline__ float ubf(unsigned short u) {
    __nv_bfloat16 b = *(__nv_bfloat16*)&u;
    return __bfloat162float(b);
}
__device__ __forceinline__ float half_of(uint32_t w, int hi) {
    return ubf((unsigned short)(hi ? (w >> 16) : (w & 0xFFFF)));
}
__device__ __forceinline__ void cp_async_tile(uint32_t dst, const unsigned char* src, int tid) {
#pragma unroll
    for (int i = 0; i < 16; i++) {
        asm volatile("cp.async.cg.shared.global [%0], [%1], 16;"
                     :: "r"(dst + (uint32_t)(tid + i * 256) * 16),
                        "l"(src + (size_t)(tid + i * 256) * 16) : "memory");
    }
    asm volatile("cp.async.commit_group;" ::: "memory");
}
__device__ __forceinline__ void cp_async_wait0() {
    asm volatile("cp.async.wait_group 0;" ::: "memory");
}

// ---------------- consolidated weight repacks ----------------
// standard slots 0..7: CI=256, NK=9, 36 subs each at slot*36*65536
// slot (index 8 in ptr array): CI=32 NK=9, 9 subs at 324*65536
__global__ void repack_all_kernel(WPtrs P, unsigned char* __restrict__ wp) {
    const int BIG = 8 * 36 * 16384;
    int idx = blockIdx.x * blockDim.x + threadIdx.x;
    if (idx < BIG) {
        int slot = idx / (36 * 16384);
        int r = idx - slot * (36 * 16384);
        int kc = r & 63;
        int oc = (r >> 6) & 255;
        int sub = r >> 14;
        int tap = sub >> 2, cc2 = sub & 3;
        int ci = (cc2 << 6) + kc;
        float v = P.w[slot][((size_t)oc * 256 + ci) * 9 + tap];
        __nv_bfloat16 hb = __float2bfloat16(v);
        __nv_bfloat16 lb = __float2bfloat16(v - __bfloat162float(hb));
        int half = oc >> 7, ocl = oc & 127;
        uint32_t ofs = (uint32_t)ocl * 128u + (((uint32_t)kc * 2u) ^ (((uint32_t)ocl & 7u) << 4));
        size_t base = (size_t)(slot * 36 + sub) * 65536 + (size_t)(half * 2) * 16384;
        *(unsigned short*)(wp + base + ofs) = *(unsigned short*)&hb;
        *(unsigned short*)(wp + base + 16384 + ofs) = *(unsigned short*)&lb;
    } else {
        int r = idx - BIG;
        if (r >= 9 * 16384) return;
        int kc = r & 63;
        int oc = (r >> 6) & 255;
        int tap = r >> 14;
        int ci = kc;
        float v = (ci < 32) ? P.w[8][((size_t)oc * 32 + ci) * 9 + tap] : 0.f;
        __nv_bfloat16 hb = __float2bfloat16(v);
        __nv_bfloat16 lb = __float2bfloat16(v - __bfloat162float(hb));
        int half = oc >> 7, ocl = oc & 127;
        uint32_t ofs = (uint32_t)ocl * 128u + (((uint32_t)kc * 2u) ^ (((uint32_t)ocl & 7u) << 4));
        size_t base = (size_t)(324 + tap) * 65536 + (size_t)(half * 2) * 16384;
        *(unsigned short*)(wp + base + ofs) = *(unsigned short*)&hb;
        *(unsigned short*)(wp + base + 16384 + ofs) = *(unsigned short*)&lb;
    }
}

// OR-conv: rotated ring source tap, 36 subs at 288*65536
__global__ void repack_or_tc_kernel(const float* __restrict__ w,
                                    unsigned char* __restrict__ wp) {
    int idx = blockIdx.x * blockDim.x + threadIdx.x;
    if (idx >= 36 * 16384) return;
    int kc = idx & 63;
    int oc = (idx >> 6) & 255;
    int sub = idx >> 14;
    int tap = sub >> 2, cc2 = sub & 3;
    int ci = (cc2 << 6) + kc;
    int o = oc >> 3, r = oc & 7;
    int s;
    if (tap == 4) {
        s = 4;
    } else {
        int j = 0;
#pragma unroll
        for (int t = 0; t < 8; t++)
            if (c_ring[t] == tap) j = t;
        s = c_ring[(j - r + 8) & 7];
    }
    float v = w[((size_t)o * CC + ci) * 9 + s];
    __nv_bfloat16 hb = __float2bfloat16(v);
    __nv_bfloat16 lb = __float2bfloat16(v - __bfloat162float(hb));
    int half = oc >> 7, ocl = oc & 127;
    uint32_t ofs = (uint32_t)ocl * 128u + (((uint32_t)kc * 2u) ^ (((uint32_t)ocl & 7u) << 4));
    size_t base = (size_t)(288 + sub) * 65536 + (size_t)(half * 2) * 16384;
    *(unsigned short*)(wp + base + ofs) = *(unsigned short*)&hb;
    *(unsigned short*)(wp + base + 16384 + ofs) = *(unsigned short*)&lb;
}

// head weights: 4 regions in g_wt_small
// [0,4096) fam_reg_hw OC5 NK1 | [4096,8192) fam_cls_hw OC15 NK1
// [8192,45056) odm_cls_hw OC15 NK9 | [45056,81920) odm_reg_hw OC5 NK9
__global__ void repack_heads_kernel(const float* __restrict__ w0, const float* __restrict__ w1,
                                    const float* __restrict__ w2, const float* __restrict__ w3,
                                    float* __restrict__ wt) {
    int idx = blockIdx.x * blockDim.x + threadIdx.x;
    if (idx >= 81920) return;
    const float* w;
    int OC, NK, r;
    if (idx < 4096) { w = w0; OC = 5; NK = 1; r = idx; }
    else if (idx < 8192) { w = w1; OC = 15; NK = 1; r = idx - 4096; }
    else if (idx < 45056) { w = w2; OC = 15; NK = 9; r = idx - 8192; }
    else { w = w3; OC = 5; NK = 9; r = idx - 45056; }
    int oc = r & 15;
    int ci = (r >> 4) & 255;
    int k = r >> 12;
    wt[idx] = (oc < OC) ? w[((size_t)oc * 256 + ci) * NK + k] : 0.f;
}

// ---------------- fp32 [C][HW] -> pair-interleaved u32 words ----------------
__global__ void cvt_pair_kernel(const float* __restrict__ x,
                                uint32_t* __restrict__ h, uint32_t* __restrict__ l,
                                int nwords) {
    int i = blockIdx.x * blockDim.x + threadIdx.x;
    if (i >= nwords) return;
    int cp = i >> 14, p = i & 16383;
    float v0 = x[(size_t)(cp * 2) * HW + p];
    float v1 = x[(size_t)(cp * 2 + 1) * HW + p];
    unsigned short h0 = bf16u(v0), h1 = bf16u(v1);
    float l0f = v0 - ubf(h0), l1f = v1 - ubf(h1);
    h[i] = (uint32_t)h0 | ((uint32_t)h1 << 16);
    l[i] = (uint32_t)bf16u(l0f) | ((uint32_t)bf16u(l1f) << 16);
}

// ---------------- shared MMA core pieces ----------------
__device__ __forceinline__ void mma_substage(uint32_t aA, uint32_t aB, int half,
                                             int mrow0, int nbase, int lrow, int lcol16,
                                             float acc[4][8][4]) {
#pragma unroll
    for (int ks = 0; ks < 4; ks++) {
        int kb = ks * 32;
        uint32_t Ah[4][4], Al[4][4];
#pragma unroll
        for (int mt = 0; mt < 4; mt++) {
            int row = mrow0 + mt * 16 + lrow;
            uint32_t roff = (uint32_t)row * 128u +
                            (((uint32_t)(kb + lcol16)) ^ (((uint32_t)row & 7u) << 4));
            ldm4(Ah[mt], aA + (half * 2 + 0) * 16384 + roff);
            ldm4(Al[mt], aA + (half * 2 + 1) * 16384 + roff);
        }
        {
            uint32_t Bh[4][4];
#pragma unroll
            for (int nt = 0; nt < 4; nt++) {
                int row = nbase + nt * 16 + lrow;
                uint32_t roff = (uint32_t)row * 128u +
                                (((uint32_t)(kb + lcol16)) ^ (((uint32_t)row & 7u) << 4));
                ldm4(Bh[nt], aB + roff);
            }
#pragma unroll
            for (int mt = 0; mt < 4; mt++)
#pragma unroll
                for (int nt = 0; nt < 4; nt++) {
                    mma_bf16(acc[mt][nt * 2 + 0], Ah[mt], Bh[nt][0], Bh[nt][2]);
                    mma_bf16(acc[mt][nt * 2 + 0], Al[mt], Bh[nt][0], Bh[nt][2]);
                    mma_bf16(acc[mt][nt * 2 + 1], Ah[mt], Bh[nt][1], Bh[nt][3]);
                    mma_bf16(acc[mt][nt * 2 + 1], Al[mt], Bh[nt][1], Bh[nt][3]);
                }
        }
        {
            uint32_t Bl[4][4];
#pragma unroll
            for (int nt = 0; nt < 4; nt++) {
                int row = nbase + nt * 16 + lrow;
                uint32_t roff = (uint32_t)row * 128u +
                                (((uint32_t)(kb + lcol16)) ^ (((uint32_t)row & 7u) << 4));
                ldm4(Bl[nt], aB + 16384 + roff);
            }
#pragma unroll
            for (int mt = 0; mt < 4; mt++)
#pragma unroll
                for (int nt = 0; nt < 4; nt++) {
                    mma_bf16(acc[mt][nt * 2 + 0], Ah[mt], Bl[nt][0], Bl[nt][2]);
                    mma_bf16(acc[mt][nt * 2 + 1], Ah[mt], Bl[nt][1], Bl[nt][3]);
                }
        }
    }
}

__device__ __forceinline__ void mma_epilogue(float acc[4][8][4], int mbase, int nbase,
                                             int lane, int y, const float* bias,
                                             int relu, int bias_div, int writeF, int writeP,
                                             float* Yf, unsigned short* Yh,
                                             unsigned short* Yl) {
    int qr = lane >> 2, qc = lane & 3;
#pragma unroll
    for (int mt = 0; mt < 4; mt++) {
#pragma unroll
        for (int nf = 0; nf < 8; nf++) {
#pragma unroll
            for (int p = 0; p < 2; p++) {
                int oc = mbase + mt * 16 + qr + p * 8;
                int pxo = nbase + nf * 8 + qc * 2;
                float bv = bias[oc / bias_div];
                float v0 = acc[mt][nf][p * 2 + 0] + bv;
                float v1 = acc[mt][nf][p * 2 + 1] + bv;
                if (relu) { v0 = fmaxf(v0, 0.f); v1 = fmaxf(v1, 0.f); }
                if (writeF) {
                    *(float2*)(Yf + (size_t)oc * HW + (size_t)y * Ww + pxo) =
                        make_float2(v0, v1);
                }
                if (writeP) {
                    size_t w0 = (size_t)(oc >> 1) * HW + (size_t)y * Ww + pxo;
                    int hb = oc & 1;
                    unsigned short h0 = bf16u(v0), h1 = bf16u(v1);
                    Yh[w0 * 2 + hb] = h0;
                    Yh[(w0 + 1) * 2 + hb] = h1;
                    Yl[w0 * 2 + hb] = bf16u(v0 - ubf(h0));
                    Yl[(w0 + 1) * 2 + hb] = bf16u(v1 - ubf(h1));
                }
            }
        }
    }
}

__device__ __forceinline__ void load_bregs(const uint32_t* __restrict__ Xrole,
                                           int y, int px, int sub, int ncc, int CI,
                                           uint32_t breg[8][4]) {
    int tap = sub / ncc;
    int ci0 = (sub - tap * ncc) << 6;
    int dy = tap / 3 - 1, dx = tap % 3 - 1;
    int ysrc = y + dy, xsrc = px + dx;
    bool ok = (ysrc >= 0) && (ysrc < Hh) && (xsrc >= 0) && (xsrc < Ww);
    int poff = ysrc * Ww + xsrc;
    int prb = ci0 >> 1;
#pragma unroll
    for (int g = 0; g < 8; g++) {
#pragma unroll
        for (int q = 0; q < 4; q++) {
            int ci = ci0 + (g * 4 + q) * 2;
            breg[g][q] = (ok && ci < CI) ? Xrole[(size_t)(prb + g * 4 + q) * HW + poff] : 0u;
        }
    }
}

// ---------------- HMMA conv: pipelined A (cp.async dbuf) + B (reg prefetch, dbuf) --
#define SMEMH 196608
__global__ void __launch_bounds__(256, 1)
conv_hmma_kernel(const unsigned char* __restrict__ wpack,
                 const uint32_t* __restrict__ Xh, const uint32_t* __restrict__ Xl,
                 const float* __restrict__ bias, float* __restrict__ Yf,
                 unsigned short* __restrict__ Yh, unsigned short* __restrict__ Yl,
                 int CI, int relu, int bias_div, int writeF, int writeP) {
    extern __shared__ unsigned char sm[];
    uint32_t aSm = smem_u32(sm);

    int tid = threadIdx.x;
    int y = blockIdx.x;
    int lane = tid & 31, wid = tid >> 5;
    int wm = wid >> 1, wn = wid & 1;
    int mbase = wm * 64;
    int half = mbase >> 7;
    int mrow0 = mbase & 127;
    int nbase = wn * 64;
    int lrow = (lane & 7) + ((lane >> 3) & 1) * 8;
    int lcol16 = (lane >> 4) * 16;
    int role = tid >> 7;
    int px = tid & 127;
    int ncc = (CI + 63) >> 6;
    int nsub = 9 * ncc;
    uint32_t bofs[8];
#pragma unroll
    for (int g = 0; g < 8; g++)
        bofs[g] = (uint32_t)px * 128u + (((uint32_t)g << 4) ^ (((uint32_t)px & 7u) << 4)) +
                  role * 16384u;

    float acc[4][8][4];
#pragma unroll
    for (int a = 0; a < 4; a++)
#pragma unroll
        for (int b = 0; b < 8; b++)
#pragma unroll
            for (int c = 0; c < 4; c++) acc[a][b][c] = 0.f;

    const uint32_t* Xrole = role ? Xl : Xh;

    uint32_t breg[8][4];
    load_bregs(Xrole, y, px, 0, ncc, CI, breg);
    cp_async_tile(aSm, wpack, tid);  // A[0]

    for (int sub = 0; sub < nsub; sub++) {
        uint32_t aA = aSm + (uint32_t)(sub & 1) * 65536u;
        uint32_t aB = aSm + 131072u + (uint32_t)(sub & 1) * 32768u;
        // store prefetched B regs
#pragma unroll
        for (int g = 0; g < 8; g++)
            *(uint4*)(sm + (aB - aSm) + bofs[g]) = make_uint4(breg[g][0], breg[g][1],
                                                              breg[g][2], breg[g][3]);
        cp_async_wait0();   // A[sub] resident
        __syncthreads();    // B[sub] visible; prior MMA done with both alt buffers
        if (sub + 1 < nsub) {
            cp_async_tile(aSm + (uint32_t)((sub + 1) & 1) * 65536u,
                          wpack + (size_t)(sub + 1) * 65536, tid);
            load_bregs(Xrole, y, px, sub + 1, ncc, CI, breg);  // overlaps MMA below
        }
        mma_substage(aA, aB, half, mrow0, nbase, lrow, lcol16, acc);
    }

    mma_epilogue(acc, mbase, nbase, lane, y, bias, relu, bias_div, writeF, writeP,
                 Yf, Yh, Yl);
}

// ---------------- deformable HMMA conv (bilinear gather B), pipelined ----------
#define SMEMD 224256
__global__ void __launch_bounds__(256, 1)
conv_deform_kernel(const unsigned char* __restrict__ wpack,
                   const float* __restrict__ feats, const float* __restrict__ refine,
                   const float* __restrict__ bias,
                   unsigned short* __restrict__ Yh, unsigned short* __restrict__ Yl) {
    extern __shared__ unsigned char sm[];
    uint32_t aSm = smem_u32(sm);
    unsigned short* s_idx = (unsigned short*)(sm + 196608);           // [36][128]
    float* s_wt = (float*)(sm + 196608 + 9216);                       // [36*4... [144][128]

    int tid = threadIdx.x;
    int y = blockIdx.x;
    int lane = tid & 31, wid = tid >> 5;
    int wm = wid >> 1, wn = wid & 1;
    int mbase = wm * 64;
    int half = mbase >> 7;
    int mrow0 = mbase & 127;
    int nbase = wn * 64;
    int lrow = (lane & 7) + ((lane >> 3) & 1) * 8;
    int lcol16 = (lane >> 4) * 16;
    int role = tid >> 7;
    int px = tid & 127;
    uint32_t bofs[8];
#pragma unroll
    for (int g = 0; g < 8; g++)
        bofs[g] = (uint32_t)px * 128u + (((uint32_t)g << 4) ^ (((uint32_t)px & 7u) << 4));

    // bilinear tables for this row (idx u16, weight fp32)
    for (int e = tid; e < 128 * 9; e += 256) {
        int pxe = e / 9, k = e % 9;
        int p = y * Ww + pxe;
        float axc = refine[p * 5 + 0] * 0.125f;
        float ayc = refine[p * 5 + 1] * 0.125f;
        float aw = refine[p * 5 + 2] * 0.125f;
        float ah = refine[p * 5 + 3] * 0.125f;
        float aa = refine[p * 5 + 4];
        float cs = cosf(aa), sn = sinf(aa);
        float kx = (float)(k % 3 - 1);
        float ky = (float)(k / 3 - 1);
        float ddx = (aw * (1.f / 3.f)) * kx;
        float ddy = (ah * (1.f / 3.f)) * ky;
        float xs = cs * ddx - sn * ddy + axc;
        float ys = sn * ddx + cs * ddy + ayc;
        float x0f = floorf(xs), y0f = floorf(ys);
        float wx1 = xs - x0f, wx0 = 1.f - wx1;
        float wy1 = ys - y0f, wy0 = 1.f - wy1;
        int x0 = (int)x0f, y0 = (int)y0f;
#pragma unroll
        for (int c = 0; c < 4; c++) {
            int xi = x0 + (c & 1);
            int yi = y0 + (c >> 1);
            float ww = ((c & 1) ? wx1 : wx0) * ((c >> 1) ? wy1 : wy0);
            bool valid = (xi >= 0 && xi < Ww && yi >= 0 && yi < Hh);
            int xc = min(max(xi, 0), Ww - 1);
            int yc = min(max(yi, 0), Hh - 1);
            s_idx[(k * 4 + c) * 128 + pxe] = (unsigned short)(yc * Ww + xc);
            s_wt[(k * 4 + c) * 128 + pxe] = valid ? ww : 0.f;
        }
    }

    float acc[4][8][4];
#pragma unroll
    for (int a = 0; a < 4; a++)
#pragma unroll
        for (int b = 0; b < 8; b++)
#pragma unroll
            for (int c = 0; c < 4; c++) acc[a][b][c] = 0.f;

    cp_async_tile(aSm, wpack, tid);
    __syncthreads();  // tables visible

    // gather for sub 0
    uint32_t hv[16], lv[16];
    {
        int tap = 0, ci0 = 0;
        int I0 = s_idx[(tap * 4 + 0) * 128 + px];
        int I1 = s_idx[(tap * 4 + 1) * 128 + px];
        int I2 = s_idx[(tap * 4 + 2) * 128 + px];
        int I3 = s_idx[(tap * 4 + 3) * 128 + px];
        float W0 = s_wt[(tap * 4 + 0) * 128 + px];
        float W1 = s_wt[(tap * 4 + 1) * 128 + px];
        float W2 = s_wt[(tap * 4 + 2) * 128 + px];
        float W3 = s_wt[(tap * 4 + 3) * 128 + px];
        int cbase = ci0 + role * 32;
#pragma unroll
        for (int j = 0; j < 16; j++) {
            const float* f0 = feats + (size_t)(cbase + j * 2) * HW;
            const float* f1 = feats + (size_t)(cbase + j * 2 + 1) * HW;
            float v0 = f0[I0] * W0 + f0[I1] * W1 + f0[I2] * W2 + f0[I3] * W3;
            float v1 = f1[I0] * W0 + f1[I1] * W1 + f1[I2] * W2 + f1[I3] * W3;
            unsigned short h0 = bf16u(v0), h1 = bf16u(v1);
            hv[j] = (uint32_t)h0 | ((uint32_t)h1 << 16);
            lv[j] = (uint32_t)bf16u(v0 - ubf(h0)) | ((uint32_t)bf16u(v1 - ubf(h1)) << 16);
        }
    }

    for (int sub = 0; sub < 36; sub++) {
        uint32_t aA = aSm + (uint32_t)(sub & 1) * 65536u;
        uint32_t aB = aSm + 131072u + (uint32_t)(sub & 1) * 32768u;
        // store gathered regs: role writes groups role*4..role*4+3, hi and lo
#pragma unroll
        for (int gg = 0; gg < 4; gg++) {
            uint32_t ofs = (uint32_t)px * 128u +
                           (((uint32_t)(role * 4 + gg) << 4) ^ (((uint32_t)px & 7u) << 4));
            *(uint4*)(sm + (aB - aSm) + ofs) = *(uint4*)&hv[gg * 4];
            *(uint4*)(sm + (aB - aSm) + 16384 + ofs) = *(uint4*)&lv[gg * 4];
        }
        cp_async_wait0();
        __syncthreads();
        if (sub + 1 < 36) {
            cp_async_tile(aSm + (uint32_t)((sub + 1) & 1) * 65536u,
                          wpack + (size_t)(sub + 1) * 65536, tid);
            int tap = (sub + 1) >> 2;
            int ci0 = ((sub + 1) & 3) << 6;
            int I0 = s_idx[(tap * 4 + 0) * 128 + px];
            int I1 = s_idx[(tap * 4 + 1) * 128 + px];
            int I2 = s_idx[(tap * 4 + 2) * 128 + px];
            int I3 = s_idx[(tap * 4 + 3) * 128 + px];
            float W0 = s_wt[(tap * 4 + 0) * 128 + px];
            float W1 = s_wt[(tap * 4 + 1) * 128 + px];
            float W2 = s_wt[(tap * 4 + 2) * 128 + px];
            float W3 = s_wt[(tap * 4 + 3) * 128 + px];
            int cbase = ci0 + role * 32;
#pragma unroll
            for (int j = 0; j < 16; j++) {
                const float* f0 = feats + (size_t)(cbase + j * 2) * HW;
                const float* f1 = feats + (size_t)(cbase + j * 2 + 1) * HW;
                float v0 = f0[I0] * W0 + f0[I1] * W1 + f0[I2] * W2 + f0[I3] * W3;
                float v1 = f1[I0] * W0 + f1[I1] * W1 + f1[I2] * W2 + f1[I3] * W3;
                unsigned short h0 = bf16u(v0), h1 = bf16u(v1);
                hv[j] = (uint32_t)h0 | ((uint32_t)h1 << 16);
                lv[j] = (uint32_t)bf16u(v0 - ubf(h0)) | ((uint32_t)bf16u(v1 - ubf(h1)) << 16);
            }
        }
        mma_substage(aA, aB, half, mrow0, nbase, lrow, lcol16, acc);
    }

    mma_epilogue(acc, mbase, nbase, lane, y, bias, 1, 1, 0, 1, (float*)0, Yh, Yl);
}

// ---------------- head partial conv (one 3x3 tap per block) ----------------
__global__ void __launch_bounds__(128, 4)
head_part_kernel(const float* __restrict__ wt, const float* __restrict__ X,
                 float* __restrict__ part, int CI, int NK) {
    __shared__ float Ws[8][16];
    __shared__ float Xs[8][128];

    int y = blockIdx.x;
    int k = blockIdx.y;
    int tid = threadIdx.x;
    int tx = tid & 31;
    int ty = tid >> 5;

    float acc[4][4];
#pragma unroll
    for (int i = 0; i < 4; i++)
#pragma unroll
        for (int j = 0; j < 4; j++) acc[i][j] = 0.f;

    int dy = (NK == 9) ? (k / 3 - 1) : 0;
    int dx = (NK == 9) ? (k % 3 - 1) : 0;
    int yy = y + dy;
    bool rowok = (yy >= 0 && yy < Hh);

    for (int ci0 = 0; ci0 < CI; ci0 += 8) {
        {
            int kk = tid >> 4;
            int m = tid & 15;
            Ws[kk][m] = wt[((size_t)(k * CI + ci0 + kk)) * 16 + m];
        }
        {
            int kk = tid >> 4;
            int lanex = tid & 15;
            const float* xrow = X + (size_t)(ci0 + kk) * HW + yy * Ww;
#pragma unroll
            for (int j = 0; j < 8; j++) {
                int n = lanex + 16 * j;
                int xx = n + dx;
                float v = 0.f;
                if (rowok && xx >= 0 && xx < Ww) v = xrow[xx];
                Xs[kk][n] = v;
            }
        }
        __syncthreads();
#pragma unroll
        for (int kk = 0; kk < 8; kk++) {
            float a[4], b[4];
            *(float4*)a = *(const float4*)&Ws[kk][ty * 4];
            *(float4*)b = *(const float4*)&Xs[kk][tx * 4];
#pragma unroll
            for (int i = 0; i < 4; i++)
#pragma unroll
                for (int j = 0; j < 4; j++) acc[i][j] += a[i] * b[j];
        }
        __syncthreads();
    }

#pragma unroll
    for (int i = 0; i < 4; i++) {
        int m = ty * 4 + i;
#pragma unroll
        for (int j = 0; j < 4; j++) {
            int n = tx * 4 + j;
            part[((size_t)k * 16 + m) * HW + (size_t)y * Ww + n] = acc[i][j];
        }
    }
}

__global__ void head_reduce_kernel(const float* __restrict__ part,
                                   const float* __restrict__ bias,
                                   float* __restrict__ Y, int OC, int NK) {
    int idx = blockIdx.x * blockDim.x + threadIdx.x;
    if (idx >= OC * HW) return;
    int m = idx / HW, p = idx - m * HW;
    float s = bias[m];
    for (int t = 0; t < NK; t++) s += part[((size_t)t * 16 + m) * HW + p];
    Y[(size_t)m * HW + p] = s;
}

// ---------------- anchors + rbox decode ----------------
__global__ void decode_kernel(const float* __restrict__ bbox,
                              float* __restrict__ anchors_out,
                              float* __restrict__ refine_out) {
    int p = blockIdx.x * blockDim.x + threadIdx.x;
    if (p >= HW) return;
    int x = p & 127, yv = p >> 7;
    float ax = x * 8.f + 3.5f;
    float ay = yv * 8.f + 3.5f;
    anchors_out[p * 5 + 0] = ax;
    anchors_out[p * 5 + 1] = ay;
    anchors_out[p * 5 + 2] = 32.f;
    anchors_out[p * 5 + 3] = 32.f;
    anchors_out[p * 5 + 4] = 0.f;

    float dx = bbox[p];
    float dyv = bbox[HW + p];
    float dw = bbox[2 * HW + p];
    float dh = bbox[3 * HW + p];
    float dt = bbox[4 * HW + p];
    const float MR = 13.815510557964274f;
    dw = fminf(fmaxf(dw, -MR), MR);
    dh = fminf(fmaxf(dh, -MR), MR);
    float gx = dx * 32.f + ax;
    float gy = dyv * 32.f + ay;
    float gw = 32.f * expf(dw);
    float gh = 32.f * expf(dh);
    const float PI = 3.14159265358979323846f;
    float r = fmodf(dt + PI * 0.25f, PI);
    if (r < 0.f) r += PI;
    float ga = r - PI * 0.25f;
    refine_out[p * 5 + 0] = gx;
    refine_out[p * 5 + 1] = gy;
    refine_out[p * 5 + 2] = gw;
    refine_out[p * 5 + 3] = gh;
    refine_out[p * 5 + 4] = ga;
}

// ---------------- rotation-invariant max pooling on pair tensors ----------------
__global__ void maxpool8_kernel(const uint32_t* __restrict__ oh,
                                const uint32_t* __restrict__ ol,
                                unsigned short* __restrict__ ph,
                                unsigned short* __restrict__ pl) {
    int p = blockIdx.x * blockDim.x + threadIdx.x;
    int i = blockIdx.y;
    if (p >= HW) return;
    float m = -1e30f;
#pragma unroll
    for (int r2 = 0; r2 < 4; r2++) {
        size_t w = (size_t)(i * 4 + r2) * HW + p;
        uint32_t wh = oh[w], wl = ol[w];
        float v0 = half_of(wh, 0) + half_of(wl, 0);
        float v1 = half_of(wh, 1) + half_of(wl, 1);
        m = fmaxf(m, fmaxf(v0, v1));
    }
    size_t wo = ((size_t)(i >> 1) * HW + p) * 2 + (i & 1);
    unsigned short hb = bf16u(m);
    ph[wo] = hb;
    pl[wo] = bf16u(m - ubf(hb));
}

// ---------------- host orchestration ----------------
extern "C" void kernel_launch(void* const* d_in, const int* in_sizes, int n_in,
                              void* d_out, int out_size) {
    (void)in_sizes; (void)n_in; (void)out_size;

    const float* feats = (const float*)d_in[0];
    const float* fam_reg_w0 = (const float*)d_in[1];
    const float* fam_reg_b0 = (const float*)d_in[2];
    const float* fam_reg_w1 = (const float*)d_in[3];
    const float* fam_reg_b1 = (const float*)d_in[4];
    const float* fam_reg_hw = (const float*)d_in[5];
    const float* fam_reg_hb = (const float*)d_in[6];
    const float* fam_cls_w0 = (const float*)d_in[7];
    const float* fam_cls_b0 = (const float*)d_in[8];
    const float* fam_cls_w1 = (const float*)d_in[9];
    const float* fam_cls_b1 = (const float*)d_in[10];
    const float* fam_cls_hw = (const float*)d_in[11];
    const float* fam_cls_hb = (const float*)d_in[12];
    const float* align_w = (const float*)d_in[13];
    const float* align_b = (const float*)d_in[14];
    const float* or_w = (const float*)d_in[15];
    const float* or_b = (const float*)d_in[16];
    const float* odm_reg_w0 = (const float*)d_in[17];
    const float* odm_reg_b0 = (const float*)d_in[18];
    const float* odm_reg_w1 = (const float*)d_in[19];
    const float* odm_reg_b1 = (const float*)d_in[20];
    const float* odm_reg_hw = (const float*)d_in[21];
    const float* odm_reg_hb = (const float*)d_in[22];
    const float* odm_cls_w0 = (const float*)d_in[23];
    const float* odm_cls_b0 = (const float*)d_in[24];
    const float* odm_cls_w1 = (const float*)d_in[25];
    const float* odm_cls_b1 = (const float*)d_in[26];
    const float* odm_cls_hw = (const float*)d_in[27];
    const float* odm_cls_hb = (const float*)d_in[28];

    float* out = (float*)d_out;
    float* o_famcls = out;
    float* o_fambbox = out + 245760;
    float* o_odmcls = out + 327680;
    float* o_odmbbox = out + 573440;
    float* o_anchors = out + 655360;
    float* o_refine = out + 737280;

    float *b1, *b2, *wts, *hd;
    unsigned char* wp;
    uint32_t *p0h, *p0l, *p1h, *p1l, *p2h, *p2l, *p3h, *p3l, *pdh, *pdl;
    cudaGetSymbolAddress((void**)&b1, g_b1);
    cudaGetSymbolAddress((void**)&b2, g_b2);
    cudaGetSymbolAddress((void**)&hd, g_head);
    cudaGetSymbolAddress((void**)&wts, g_wt_small);
    cudaGetSymbolAddress((void**)&wp, g_wpack);
    cudaGetSymbolAddress((void**)&p0h, g_p0h);
    cudaGetSymbolAddress((void**)&p0l, g_p0l);
    cudaGetSymbolAddress((void**)&p1h, g_p1h);
    cudaGetSymbolAddress((void**)&p1l, g_p1l);
    cudaGetSymbolAddress((void**)&p2h, g_p2h);
    cudaGetSymbolAddress((void**)&p2l, g_p2l);
    cudaGetSymbolAddress((void**)&p3h, g_p3h);
    cudaGetSymbolAddress((void**)&p3l, g_p3l);
    cudaGetSymbolAddress((void**)&pdh, g_pdh);
    cudaGetSymbolAddress((void**)&pdl, g_pdl);

    cudaFuncSetAttribute(conv_hmma_kernel, cudaFuncAttributeMaxDynamicSharedMemorySize, SMEMH);
    cudaFuncSetAttribute(conv_deform_kernel, cudaFuncAttributeMaxDynamicSharedMemorySize, SMEMD);

    const size_t SLOT = 36 * 65536;

    // 1: feats -> pair P0
    cvt_pair_kernel<<<8192, 256>>>(feats, p0h, p0l, 128 * HW);

    // 2-4: all weight repacks up front
    {
        WPtrs P;
        P.w[0] = fam_reg_w0; P.w[1] = fam_reg_w1; P.w[2] = fam_cls_w0; P.w[3] = fam_cls_w1;
        P.w[4] = align_w; P.w[5] = odm_cls_w1; P.w[6] = odm_reg_w0; P.w[7] = odm_reg_w1;
        P.w[8] = odm_cls_w0;
        repack_all_kernel<<<(8 * 36 * 16384 + 9 * 16384 + 255) / 256, 256>>>(P, wp);
    }
    repack_or_tc_kernel<<<2304, 256>>>(or_w, wp);
    repack_heads_kernel<<<320, 256>>>(fam_reg_hw, fam_cls_hw, odm_cls_hw, odm_reg_hw, wts);

    // 5-8: FAM convs
    conv_hmma_kernel<<<128, 256, SMEMH>>>(wp + 0 * SLOT, p0h, p0l, fam_reg_b0, b1,
                                          (unsigned short*)p1h, (unsigned short*)p1l,
                                          256, 1, 1, 0, 1);
    conv_hmma_kernel<<<128, 256, SMEMH>>>(wp + 1 * SLOT, p1h, p1l, fam_reg_b1, b1,
                                          (unsigned short*)p2h, (unsigned short*)p2l,
                                          256, 1, 1, 1, 0);
    conv_hmma_kernel<<<128, 256, SMEMH>>>(wp + 2 * SLOT, p0h, p0l, fam_cls_b0, b2,
                                          (unsigned short*)p2h, (unsigned short*)p2l,
                                          256, 1, 1, 0, 1);
    conv_hmma_kernel<<<128, 256, SMEMH>>>(wp + 3 * SLOT, p2h, p2l, fam_cls_b1, b2,
                                          (unsigned short*)p3h, (unsigned short*)p3l,
                                          256, 1, 1, 1, 0);

    // 9-12: FAM heads (b1 -> fambbox, b2 -> famcls)
    head_part_kernel<<<dim3(128, 1), 128>>>(wts + 0, b1, hd, 256, 1);
    head_reduce_kernel<<<(5 * HW + 255) / 256, 256>>>(hd, fam_reg_hb, o_fambbox, 5, 1);
    head_part_kernel<<<dim3(128, 1), 128>>>(wts + 4096, b2, hd, 256, 1);
    head_reduce_kernel<<<(15 * HW + 255) / 256, 256>>>(hd, fam_cls_hb, o_famcls, 15, 1);

    // 13: anchors + decode
    decode_kernel<<<HW / 256, 256>>>(o_fambbox, o_anchors, o_refine);

    // 14: deformable align conv: feats -> pair P1
    conv_deform_kernel<<<128, 256, SMEMD>>>(wp + 4 * SLOT, feats, o_refine, align_b,
                                            (unsigned short*)p1h, (unsigned short*)p1l);

    // 15: OR conv: P1 -> pair P2
    conv_hmma_kernel<<<128, 256, SMEMH>>>(wp + 8 * SLOT, p1h, p1l, or_b, b1,
                                          (unsigned short*)p2h, (unsigned short*)p2l,
                                          256, 0, 8, 0, 1);

    // 16: pooling: P2 -> PD
    {
        dim3 g(HW / 256, 32);
        maxpool8_kernel<<<g, 256>>>(p2h, p2l, (unsigned short*)pdh, (unsigned short*)pdl);
    }

    // 17-20: ODM cls branch (PD -> P3 -> b1 -> head)
    conv_hmma_kernel<<<128, 256, SMEMH>>>(wp + 9 * SLOT, pdh, pdl, odm_cls_b0, b1,
                                          (unsigned short*)p3h, (unsigned short*)p3l,
                                          32, 1, 1, 0, 1);
    conv_hmma_kernel<<<128, 256, SMEMH>>>(wp + 5 * SLOT, p3h, p3l, odm_cls_b1, b1,
                                          (unsigned short*)p1h, (unsigned short*)p1l,
                                          256, 1, 1, 1, 0);
    head_part_kernel<<<dim3(128, 9), 128>>>(wts + 8192, b1, hd, 256, 9);
    head_reduce_kernel<<<(15 * HW + 255) / 256, 256>>>(hd, odm_cls_hb, o_odmcls, 15, 9);

    // 21-24: ODM reg branch (P2 -> P3 -> b2 -> head)
    conv_hmma_kernel<<<128, 256, SMEMH>>>(wp + 6 * SLOT, p2h, p2l, odm_reg_b0, b2,
                                          (unsigned short*)p3h, (unsigned short*)p3l,
                                          256, 1, 1, 0, 1);
    conv_hmma_kernel<<<128, 256, SMEMH>>>(wp + 7 * SLOT, p3h, p3l, odm_reg_b1, b2,
                                          (unsigned short*)p1h, (unsigned short*)p1l,
                                          256, 1, 1, 1, 0);
    head_part_kernel<<<dim3(128, 9), 128>>>(wts + 45056, b2, hd, 256, 9);
    head_reduce_kernel<<<(5 * HW + 255) / 256, 256>>>(hd, odm_reg_hb, o_odmbbox, 5, 9);
}

// round 10
// speedup vs baseline: 2.6955x; 1.0472x over previous
#include <cuda_runtime.h>
#include <cuda_bf16.h>
#include <math.h>
#include <stdint.h>

#define Hh 128
#define Ww 128
#define HW 16384
#define CC 256

// ---------------- scratch (static __device__, no allocs) ----------------
__device__ float g_b1[CC * HW];
__device__ float g_b2[CC * HW];
__device__ float g_head[9 * 16 * HW];
__device__ float g_head2[9 * 16 * HW];
__device__ float g_wt_small[81920];
__device__ unsigned char g_wpack[333 * 65536];
// pair tensors: u32 word = (bf16 ch 2m) | (bf16 ch 2m+1 << 16), index m*HW + p
__device__ uint32_t g_p0h[128 * HW];
__device__ uint32_t g_p0l[128 * HW];
__device__ uint32_t g_p1h[128 * HW];
__device__ uint32_t g_p1l[128 * HW];
__device__ uint32_t g_p2h[128 * HW];
__device__ uint32_t g_p2l[128 * HW];
__device__ uint32_t g_p3h[128 * HW];
__device__ uint32_t g_p3l[128 * HW];
__device__ uint32_t g_pdh[16 * HW];
__device__ uint32_t g_pdl[16 * HW];

__constant__ int c_ring[8] = {0, 1, 2, 5, 8, 7, 6, 3};

struct WPtrs {
    const float* w[9];
};

// ---------------- helpers ----------------
__device__ __forceinline__ uint32_t smem_u32(const void* p) {
    uint32_t a;
    asm("{ .reg .u64 t; cvta.to.shared.u64 t, %1; cvt.u32.u64 %0, t; }" : "=r"(a) : "l"(p));
    return a;
}
__device__ __forceinline__ void ldm4(uint32_t* r, uint32_t addr) {
    asm volatile("ldmatrix.sync.aligned.m8n8.x4.shared.b16 {%0,%1,%2,%3}, [%4];"
                 : "=r"(r[0]), "=r"(r[1]), "=r"(r[2]), "=r"(r[3]) : "r"(addr));
}
__device__ __forceinline__ void mma_bf16(float* c, const uint32_t* a, uint32_t b0, uint32_t b1) {
    asm volatile(
        "mma.sync.aligned.m16n8k16.row.col.f32.bf16.bf16.f32 "
        "{%0,%1,%2,%3}, {%4,%5,%6,%7}, {%8,%9}, {%0,%1,%2,%3};"
        : "+f"(c[0]), "+f"(c[1]), "+f"(c[2]), "+f"(c[3])
        : "r"(a[0]), "r"(a[1]), "r"(a[2]), "r"(a[3]), "r"(b0), "r"(b1));
}
__device__ __forceinline__ unsigned short bf16u(float v) {
    __nv_bfloat16 b = __float2bfloat16(v);
    return *(unsigned short*)&b;
}
__device__ __forceinline__ float ubf(unsigned short u) {
    __nv_bfloat16 b = *(__nv_bfloat16*)&u;
    return __bfloat162float(b);
}
__device__ __forceinline__ float half_of(uint32_t w, int hi) {
    return ubf((unsigned short)(hi ? (w >> 16) : (w & 0xFFFF)));
}
__device__ __forceinline__ void cp_async_tile(uint32_t dst, const unsigned char* src, int tid) {
#pragma unroll
    for (int i = 0; i < 16; i++) {
        asm volatile("cp.async.cg.shared.global [%0], [%1], 16;"
                     :: "r"(dst + (uint32_t)(tid + i * 256) * 16),
                        "l"(src + (size_t)(tid + i * 256) * 16) : "memory");
    }
    asm volatile("cp.async.commit_group;" ::: "memory");
}
__device__ __forceinline__ void cp_async_wait0() {
    asm volatile("cp.async.wait_group 0;" ::: "memory");
}

// ---------------- consolidated weight repacks ----------------
// standard slots 0..7: CI=256, NK=9, 36 subs each at slot*36*65536
// slot (index 8 in ptr array): CI=32 NK=9, 9 subs at 324*65536
__global__ void repack_all_kernel(WPtrs P, unsigned char* __restrict__ wp) {
    const int BIG = 8 * 36 * 16384;
    int idx = blockIdx.x * blockDim.x + threadIdx.x;
    if (idx < BIG) {
        int slot = idx / (36 * 16384);
        int r = idx - slot * (36 * 16384);
        int kc = r & 63;
        int oc = (r >> 6) & 255;
        int sub = r >> 14;
        int tap = sub >> 2, cc2 = sub & 3;
        int ci = (cc2 << 6) + kc;
        float v = P.w[slot][((size_t)oc * 256 + ci) * 9 + tap];
        __nv_bfloat16 hb = __float2bfloat16(v);
        __nv_bfloat16 lb = __float2bfloat16(v - __bfloat162float(hb));
        int half = oc >> 7, ocl = oc & 127;
        uint32_t ofs = (uint32_t)ocl * 128u + (((uint32_t)kc * 2u) ^ (((uint32_t)ocl & 7u) << 4));
        size_t base = (size_t)(slot * 36 + sub) * 65536 + (size_t)(half * 2) * 16384;
        *(unsigned short*)(wp + base + ofs) = *(unsigned short*)&hb;
        *(unsigned short*)(wp + base + 16384 + ofs) = *(unsigned short*)&lb;
    } else {
        int r = idx - BIG;
        if (r >= 9 * 16384) return;
        int kc = r & 63;
        int oc = (r >> 6) & 255;
        int tap = r >> 14;
        int ci = kc;
        float v = (ci < 32) ? P.w[8][((size_t)oc * 32 + ci) * 9 + tap] : 0.f;
        __nv_bfloat16 hb = __float2bfloat16(v);
        __nv_bfloat16 lb = __float2bfloat16(v - __bfloat162float(hb));
        int half = oc >> 7, ocl = oc & 127;
        uint32_t ofs = (uint32_t)ocl * 128u + (((uint32_t)kc * 2u) ^ (((uint32_t)ocl & 7u) << 4));
        size_t base = (size_t)(324 + tap) * 65536 + (size_t)(half * 2) * 16384;
        *(unsigned short*)(wp + base + ofs) = *(unsigned short*)&hb;
        *(unsigned short*)(wp + base + 16384 + ofs) = *(unsigned short*)&lb;
    }
}

// OR-conv: rotated ring source tap, 36 subs at 288*65536
__global__ void repack_or_tc_kernel(const float* __restrict__ w,
                                    unsigned char* __restrict__ wp) {
    int idx = blockIdx.x * blockDim.x + threadIdx.x;
    if (idx >= 36 * 16384) return;
    int kc = idx & 63;
    int oc = (idx >> 6) & 255;
    int sub = idx >> 14;
    int tap = sub >> 2, cc2 = sub & 3;
    int ci = (cc2 << 6) + kc;
    int o = oc >> 3, r = oc & 7;
    int s;
    if (tap == 4) {
        s = 4;
    } else {
        int j = 0;
#pragma unroll
        for (int t = 0; t < 8; t++)
            if (c_ring[t] == tap) j = t;
        s = c_ring[(j - r + 8) & 7];
    }
    float v = w[((size_t)o * CC + ci) * 9 + s];
    __nv_bfloat16 hb = __float2bfloat16(v);
    __nv_bfloat16 lb = __float2bfloat16(v - __bfloat162float(hb));
    int half = oc >> 7, ocl = oc & 127;
    uint32_t ofs = (uint32_t)ocl * 128u + (((uint32_t)kc * 2u) ^ (((uint32_t)ocl & 7u) << 4));
    size_t base = (size_t)(288 + sub) * 65536 + (size_t)(half * 2) * 16384;
    *(unsigned short*)(wp + base + ofs) = *(unsigned short*)&hb;
    *(unsigned short*)(wp + base + 16384 + ofs) = *(unsigned short*)&lb;
}

// head weights: 4 regions in g_wt_small
// [0,4096) fam_reg_hw OC5 NK1 | [4096,8192) fam_cls_hw OC15 NK1
// [8192,45056) odm_cls_hw OC15 NK9 | [45056,81920) odm_reg_hw OC5 NK9
__global__ void repack_heads_kernel(const float* __restrict__ w0, const float* __restrict__ w1,
                                    const float* __restrict__ w2, const float* __restrict__ w3,
                                    float* __restrict__ wt) {
    int idx = blockIdx.x * blockDim.x + threadIdx.x;
    if (idx >= 81920) return;
    const float* w;
    int OC, NK, r;
    if (idx < 4096) { w = w0; OC = 5; NK = 1; r = idx; }
    else if (idx < 8192) { w = w1; OC = 15; NK = 1; r = idx - 4096; }
    else if (idx < 45056) { w = w2; OC = 15; NK = 9; r = idx - 8192; }
    else { w = w3; OC = 5; NK = 9; r = idx - 45056; }
    int oc = r & 15;
    int ci = (r >> 4) & 255;
    int k = r >> 12;
    wt[idx] = (oc < OC) ? w[((size_t)oc * 256 + ci) * NK + k] : 0.f;
}

// ---------------- fp32 [C][HW] -> pair-interleaved u32 words ----------------
__global__ void cvt_pair_kernel(const float* __restrict__ x,
                                uint32_t* __restrict__ h, uint32_t* __restrict__ l,
                                int nwords) {
    int i = blockIdx.x * blockDim.x + threadIdx.x;
    if (i >= nwords) return;
    int cp = i >> 14, p = i & 16383;
    float v0 = x[(size_t)(cp * 2) * HW + p];
    float v1 = x[(size_t)(cp * 2 + 1) * HW + p];
    unsigned short h0 = bf16u(v0), h1 = bf16u(v1);
    float l0f = v0 - ubf(h0), l1f = v1 - ubf(h1);
    h[i] = (uint32_t)h0 | ((uint32_t)h1 << 16);
    l[i] = (uint32_t)bf16u(l0f) | ((uint32_t)bf16u(l1f) << 16);
}

// ---------------- shared MMA core pieces ----------------
__device__ __forceinline__ void mma_substage(uint32_t aA, uint32_t aB, int half,
                                             int mrow0, int nbase, int lrow, int lcol16,
                                             float acc[4][8][4]) {
#pragma unroll
    for (int ks = 0; ks < 4; ks++) {
        int kb = ks * 32;
        uint32_t Ah[4][4], Al[4][4];
#pragma unroll
        for (int mt = 0; mt < 4; mt++) {
            int row = mrow0 + mt * 16 + lrow;
            uint32_t roff = (uint32_t)row * 128u +
                            (((uint32_t)(kb + lcol16)) ^ (((uint32_t)row & 7u) << 4));
            ldm4(Ah[mt], aA + (half * 2 + 0) * 16384 + roff);
            ldm4(Al[mt], aA + (half * 2 + 1) * 16384 + roff);
        }
        {
            uint32_t Bh[4][4];
#pragma unroll
            for (int nt = 0; nt < 4; nt++) {
                int row = nbase + nt * 16 + lrow;
                uint32_t roff = (uint32_t)row * 128u +
                                (((uint32_t)(kb + lcol16)) ^ (((uint32_t)row & 7u) << 4));
                ldm4(Bh[nt], aB + roff);
            }
#pragma unroll
            for (int mt = 0; mt < 4; mt++)
#pragma unroll
                for (int nt = 0; nt < 4; nt++) {
                    mma_bf16(acc[mt][nt * 2 + 0], Ah[mt], Bh[nt][0], Bh[nt][2]);
                    mma_bf16(acc[mt][nt * 2 + 0], Al[mt], Bh[nt][0], Bh[nt][2]);
                    mma_bf16(acc[mt][nt * 2 + 1], Ah[mt], Bh[nt][1], Bh[nt][3]);
                    mma_bf16(acc[mt][nt * 2 + 1], Al[mt], Bh[nt][1], Bh[nt][3]);
                }
        }
        {
            uint32_t Bl[4][4];
#pragma unroll
            for (int nt = 0; nt < 4; nt++) {
                int row = nbase + nt * 16 + lrow;
                uint32_t roff = (uint32_t)row * 128u +
                                (((uint32_t)(kb + lcol16)) ^ (((uint32_t)row & 7u) << 4));
                ldm4(Bl[nt], aB + 16384 + roff);
            }
#pragma unroll
            for (int mt = 0; mt < 4; mt++)
#pragma unroll
                for (int nt = 0; nt < 4; nt++) {
                    mma_bf16(acc[mt][nt * 2 + 0], Ah[mt], Bl[nt][0], Bl[nt][2]);
                    mma_bf16(acc[mt][nt * 2 + 1], Ah[mt], Bl[nt][1], Bl[nt][3]);
                }
        }
    }
}

__device__ __forceinline__ void mma_epilogue(float acc[4][8][4], int mbase, int nbase,
                                             int lane, int y, const float* bias,
                                             int relu, int bias_div, int writeF, int writeP,
                                             float* Yf, unsigned short* Yh,
                                             unsigned short* Yl) {
    int qr = lane >> 2, qc = lane & 3;
#pragma unroll
    for (int mt = 0; mt < 4; mt++) {
#pragma unroll
        for (int nf = 0; nf < 8; nf++) {
#pragma unroll
            for (int p = 0; p < 2; p++) {
                int oc = mbase + mt * 16 + qr + p * 8;
                int pxo = nbase + nf * 8 + qc * 2;
                float bv = bias[oc / bias_div];
                float v0 = acc[mt][nf][p * 2 + 0] + bv;
                float v1 = acc[mt][nf][p * 2 + 1] + bv;
                if (relu) { v0 = fmaxf(v0, 0.f); v1 = fmaxf(v1, 0.f); }
                if (writeF) {
                    *(float2*)(Yf + (size_t)oc * HW + (size_t)y * Ww + pxo) =
                        make_float2(v0, v1);
                }
                if (writeP) {
                    size_t w0 = (size_t)(oc >> 1) * HW + (size_t)y * Ww + pxo;
                    int hb = oc & 1;
                    unsigned short h0 = bf16u(v0), h1 = bf16u(v1);
                    Yh[w0 * 2 + hb] = h0;
                    Yh[(w0 + 1) * 2 + hb] = h1;
                    Yl[w0 * 2 + hb] = bf16u(v0 - ubf(h0));
                    Yl[(w0 + 1) * 2 + hb] = bf16u(v1 - ubf(h1));
                }
            }
        }
    }
}

__device__ __forceinline__ void load_bregs(const uint32_t* __restrict__ Xrole,
                                           int y, int px, int sub, int ncc, int CI,
                                           uint32_t breg[8][4]) {
    int tap = sub / ncc;
    int ci0 = (sub - tap * ncc) << 6;
    int dy = tap / 3 - 1, dx = tap % 3 - 1;
    int ysrc = y + dy, xsrc = px + dx;
    bool ok = (ysrc >= 0) && (ysrc < Hh) && (xsrc >= 0) && (xsrc < Ww);
    int poff = ysrc * Ww + xsrc;
    int prb = ci0 >> 1;
#pragma unroll
    for (int g = 0; g < 8; g++) {
#pragma unroll
        for (int q = 0; q < 4; q++) {
            int ci = ci0 + (g * 4 + q) * 2;
            breg[g][q] = (ok && ci < CI) ? Xrole[(size_t)(prb + g * 4 + q) * HW + poff] : 0u;
        }
    }
}

// ---------------- HMMA conv: pipelined A (cp.async dbuf) + B (reg prefetch, dbuf) --
#define SMEMH 196608
__global__ void __launch_bounds__(256, 1)
conv_hmma_kernel(const unsigned char* __restrict__ wpack,
                 const uint32_t* __restrict__ Xh, const uint32_t* __restrict__ Xl,
                 const float* __restrict__ bias, float* __restrict__ Yf,
                 unsigned short* __restrict__ Yh, unsigned short* __restrict__ Yl,
                 int CI, int relu, int bias_div, int writeF, int writeP) {
    extern __shared__ unsigned char sm[];
    uint32_t aSm = smem_u32(sm);

    int tid = threadIdx.x;
    int y = blockIdx.x;
    int lane = tid & 31, wid = tid >> 5;
    int wm = wid >> 1, wn = wid & 1;
    int mbase = wm * 64;
    int half = mbase >> 7;
    int mrow0 = mbase & 127;
    int nbase = wn * 64;
    int lrow = (lane & 7) + ((lane >> 3) & 1) * 8;
    int lcol16 = (lane >> 4) * 16;
    int role = tid >> 7;
    int px = tid & 127;
    int ncc = (CI + 63) >> 6;
    int nsub = 9 * ncc;
    uint32_t bofs[8];
#pragma unroll
    for (int g = 0; g < 8; g++)
        bofs[g] = (uint32_t)px * 128u + (((uint32_t)g << 4) ^ (((uint32_t)px & 7u) << 4)) +
                  role * 16384u;

    float acc[4][8][4];
#pragma unroll
    for (int a = 0; a < 4; a++)
#pragma unroll
        for (int b = 0; b < 8; b++)
#pragma unroll
            for (int c = 0; c < 4; c++) acc[a][b][c] = 0.f;

    const uint32_t* Xrole = role ? Xl : Xh;

    uint32_t breg[8][4];
    load_bregs(Xrole, y, px, 0, ncc, CI, breg);
    cp_async_tile(aSm, wpack, tid);  // A[0]

    for (int sub = 0; sub < nsub; sub++) {
        uint32_t aA = aSm + (uint32_t)(sub & 1) * 65536u;
        uint32_t aB = aSm + 131072u + (uint32_t)(sub & 1) * 32768u;
        // store prefetched B regs
#pragma unroll
        for (int g = 0; g < 8; g++)
            *(uint4*)(sm + (aB - aSm) + bofs[g]) = make_uint4(breg[g][0], breg[g][1],
                                                              breg[g][2], breg[g][3]);
        cp_async_wait0();   // A[sub] resident
        __syncthreads();    // B[sub] visible; prior MMA done with both alt buffers
        if (sub + 1 < nsub) {
            cp_async_tile(aSm + (uint32_t)((sub + 1) & 1) * 65536u,
                          wpack + (size_t)(sub + 1) * 65536, tid);
            load_bregs(Xrole, y, px, sub + 1, ncc, CI, breg);  // overlaps MMA below
        }
        mma_substage(aA, aB, half, mrow0, nbase, lrow, lcol16, acc);
    }

    mma_epilogue(acc, mbase, nbase, lane, y, bias, relu, bias_div, writeF, writeP,
                 Yf, Yh, Yl);
}

// ---------------- deformable HMMA conv (bilinear gather B), pipelined ----------
#define SMEMD 224256
__global__ void __launch_bounds__(256, 1)
conv_deform_kernel(const unsigned char* __restrict__ wpack,
                   const float* __restrict__ feats, const float* __restrict__ refine,
                   const float* __restrict__ bias,
                   unsigned short* __restrict__ Yh, unsigned short* __restrict__ Yl) {
    extern __shared__ unsigned char sm[];
    uint32_t aSm = smem_u32(sm);
    unsigned short* s_idx = (unsigned short*)(sm + 196608);           // [36][128]
    float* s_wt = (float*)(sm + 196608 + 9216);                       // [144][128]

    int tid = threadIdx.x;
    int y = blockIdx.x;
    int lane = tid & 31, wid = tid >> 5;
    int wm = wid >> 1, wn = wid & 1;
    int mbase = wm * 64;
    int half = mbase >> 7;
    int mrow0 = mbase & 127;
    int nbase = wn * 64;
    int lrow = (lane & 7) + ((lane >> 3) & 1) * 8;
    int lcol16 = (lane >> 4) * 16;
    int role = tid >> 7;
    int px = tid & 127;

    // bilinear tables for this row (idx u16, weight fp32)
    for (int e = tid; e < 128 * 9; e += 256) {
        int pxe = e / 9, k = e % 9;
        int p = y * Ww + pxe;
        float axc = refine[p * 5 + 0] * 0.125f;
        float ayc = refine[p * 5 + 1] * 0.125f;
        float aw = refine[p * 5 + 2] * 0.125f;
        float ah = refine[p * 5 + 3] * 0.125f;
        float aa = refine[p * 5 + 4];
        float cs = cosf(aa), sn = sinf(aa);
        float kx = (float)(k % 3 - 1);
        float ky = (float)(k / 3 - 1);
        float ddx = (aw * (1.f / 3.f)) * kx;
        float ddy = (ah * (1.f / 3.f)) * ky;
        float xs = cs * ddx - sn * ddy + axc;
        float ys = sn * ddx + cs * ddy + ayc;
        float x0f = floorf(xs), y0f = floorf(ys);
        float wx1 = xs - x0f, wx0 = 1.f - wx1;
        float wy1 = ys - y0f, wy0 = 1.f - wy1;
        int x0 = (int)x0f, y0 = (int)y0f;
#pragma unroll
        for (int c = 0; c < 4; c++) {
            int xi = x0 + (c & 1);
            int yi = y0 + (c >> 1);
            float ww = ((c & 1) ? wx1 : wx0) * ((c >> 1) ? wy1 : wy0);
            bool valid = (xi >= 0 && xi < Ww && yi >= 0 && yi < Hh);
            int xc = min(max(xi, 0), Ww - 1);
            int yc = min(max(yi, 0), Hh - 1);
            s_idx[(k * 4 + c) * 128 + pxe] = (unsigned short)(yc * Ww + xc);
            s_wt[(k * 4 + c) * 128 + pxe] = valid ? ww : 0.f;
        }
    }

    float acc[4][8][4];
#pragma unroll
    for (int a = 0; a < 4; a++)
#pragma unroll
        for (int b = 0; b < 8; b++)
#pragma unroll
            for (int c = 0; c < 4; c++) acc[a][b][c] = 0.f;

    cp_async_tile(aSm, wpack, tid);
    __syncthreads();  // tables visible

    // gather for sub 0
    uint32_t hv[16], lv[16];
    {
        int tap = 0, ci0 = 0;
        int I0 = s_idx[(tap * 4 + 0) * 128 + px];
        int I1 = s_idx[(tap * 4 + 1) * 128 + px];
        int I2 = s_idx[(tap * 4 + 2) * 128 + px];
        int I3 = s_idx[(tap * 4 + 3) * 128 + px];
        float W0 = s_wt[(tap * 4 + 0) * 128 + px];
        float W1 = s_wt[(tap * 4 + 1) * 128 + px];
        float W2 = s_wt[(tap * 4 + 2) * 128 + px];
        float W3 = s_wt[(tap * 4 + 3) * 128 + px];
        int cbase = ci0 + role * 32;
#pragma unroll
        for (int j = 0; j < 16; j++) {
            const float* f0 = feats + (size_t)(cbase + j * 2) * HW;
            const float* f1 = feats + (size_t)(cbase + j * 2 + 1) * HW;
            float v0 = f0[I0] * W0 + f0[I1] * W1 + f0[I2] * W2 + f0[I3] * W3;
            float v1 = f1[I0] * W0 + f1[I1] * W1 + f1[I2] * W2 + f1[I3] * W3;
            unsigned short h0 = bf16u(v0), h1 = bf16u(v1);
            hv[j] = (uint32_t)h0 | ((uint32_t)h1 << 16);
            lv[j] = (uint32_t)bf16u(v0 - ubf(h0)) | ((uint32_t)bf16u(v1 - ubf(h1)) << 16);
        }
    }

    for (int sub = 0; sub < 36; sub++) {
        uint32_t aA = aSm + (uint32_t)(sub & 1) * 65536u;
        uint32_t aB = aSm + 131072u + (uint32_t)(sub & 1) * 32768u;
        // store gathered regs: role writes groups role*4..role*4+3, hi and lo
#pragma unroll
        for (int gg = 0; gg < 4; gg++) {
            uint32_t ofs = (uint32_t)px * 128u +
                           (((uint32_t)(role * 4 + gg) << 4) ^ (((uint32_t)px & 7u) << 4));
            *(uint4*)(sm + (aB - aSm) + ofs) = *(uint4*)&hv[gg * 4];
            *(uint4*)(sm + (aB - aSm) + 16384 + ofs) = *(uint4*)&lv[gg * 4];
        }
        cp_async_wait0();
        __syncthreads();
        if (sub + 1 < 36) {
            cp_async_tile(aSm + (uint32_t)((sub + 1) & 1) * 65536u,
                          wpack + (size_t)(sub + 1) * 65536, tid);
            int tap = (sub + 1) >> 2;
            int ci0 = ((sub + 1) & 3) << 6;
            int I0 = s_idx[(tap * 4 + 0) * 128 + px];
            int I1 = s_idx[(tap * 4 + 1) * 128 + px];
            int I2 = s_idx[(tap * 4 + 2) * 128 + px];
            int I3 = s_idx[(tap * 4 + 3) * 128 + px];
            float W0 = s_wt[(tap * 4 + 0) * 128 + px];
            float W1 = s_wt[(tap * 4 + 1) * 128 + px];
            float W2 = s_wt[(tap * 4 + 2) * 128 + px];
            float W3 = s_wt[(tap * 4 + 3) * 128 + px];
            int cbase = ci0 + role * 32;
#pragma unroll
            for (int j = 0; j < 16; j++) {
                const float* f0 = feats + (size_t)(cbase + j * 2) * HW;
                const float* f1 = feats + (size_t)(cbase + j * 2 + 1) * HW;
                float v0 = f0[I0] * W0 + f0[I1] * W1 + f0[I2] * W2 + f0[I3] * W3;
                float v1 = f1[I0] * W0 + f1[I1] * W1 + f1[I2] * W2 + f1[I3] * W3;
                unsigned short h0 = bf16u(v0), h1 = bf16u(v1);
                hv[j] = (uint32_t)h0 | ((uint32_t)h1 << 16);
                lv[j] = (uint32_t)bf16u(v0 - ubf(h0)) | ((uint32_t)bf16u(v1 - ubf(h1)) << 16);
            }
        }
        mma_substage(aA, aB, half, mrow0, nbase, lrow, lcol16, acc);
    }

    mma_epilogue(acc, mbase, nbase, lane, y, bias, 1, 1, 0, 1, (float*)0, Yh, Yl);
}

// ---------------- head partial conv (one 3x3 tap per block) ----------------
__global__ void __launch_bounds__(128, 4)
head_part_kernel(const float* __restrict__ wt, const float* __restrict__ X,
                 float* __restrict__ part, int CI, int NK) {
    __shared__ float Ws[8][16];
    __shared__ float Xs[8][128];

    int y = blockIdx.x;
    int k = blockIdx.y;
    int tid = threadIdx.x;
    int tx = tid & 31;
    int ty = tid >> 5;

    float acc[4][4];
#pragma unroll
    for (int i = 0; i < 4; i++)
#pragma unroll
        for (int j = 0; j < 4; j++) acc[i][j] = 0.f;

    int dy = (NK == 9) ? (k / 3 - 1) : 0;
    int dx = (NK == 9) ? (k % 3 - 1) : 0;
    int yy = y + dy;
    bool rowok = (yy >= 0 && yy < Hh);

    for (int ci0 = 0; ci0 < CI; ci0 += 8) {
        {
            int kk = tid >> 4;
            int m = tid & 15;
            Ws[kk][m] = wt[((size_t)(k * CI + ci0 + kk)) * 16 + m];
        }
        {
            int kk = tid >> 4;
            int lanex = tid & 15;
            const float* xrow = X + (size_t)(ci0 + kk) * HW + yy * Ww;
#pragma unroll
            for (int j = 0; j < 8; j++) {
                int n = lanex + 16 * j;
                int xx = n + dx;
                float v = 0.f;
                if (rowok && xx >= 0 && xx < Ww) v = xrow[xx];
                Xs[kk][n] = v;
            }
        }
        __syncthreads();
#pragma unroll
        for (int kk = 0; kk < 8; kk++) {
            float a[4], b[4];
            *(float4*)a = *(const float4*)&Ws[kk][ty * 4];
            *(float4*)b = *(const float4*)&Xs[kk][tx * 4];
#pragma unroll
            for (int i = 0; i < 4; i++)
#pragma unroll
                for (int j = 0; j < 4; j++) acc[i][j] += a[i] * b[j];
        }
        __syncthreads();
    }

#pragma unroll
    for (int i = 0; i < 4; i++) {
        int m = ty * 4 + i;
#pragma unroll
        for (int j = 0; j < 4; j++) {
            int n = tx * 4 + j;
            part[((size_t)k * 16 + m) * HW + (size_t)y * Ww + n] = acc[i][j];
        }
    }
}

__global__ void head_reduce_kernel(const float* __restrict__ part,
                                   const float* __restrict__ bias,
                                   float* __restrict__ Y, int OC, int NK) {
    int idx = blockIdx.x * blockDim.x + threadIdx.x;
    if (idx >= OC * HW) return;
    int m = idx / HW, p = idx - m * HW;
    float s = bias[m];
    for (int t = 0; t < NK; t++) s += part[((size_t)t * 16 + m) * HW + p];
    Y[(size_t)m * HW + p] = s;
}

// ---------------- anchors + rbox decode ----------------
__global__ void decode_kernel(const float* __restrict__ bbox,
                              float* __restrict__ anchors_out,
                              float* __restrict__ refine_out) {
    int p = blockIdx.x * blockDim.x + threadIdx.x;
    if (p >= HW) return;
    int x = p & 127, yv = p >> 7;
    float ax = x * 8.f + 3.5f;
    float ay = yv * 8.f + 3.5f;
    anchors_out[p * 5 + 0] = ax;
    anchors_out[p * 5 + 1] = ay;
    anchors_out[p * 5 + 2] = 32.f;
    anchors_out[p * 5 + 3] = 32.f;
    anchors_out[p * 5 + 4] = 0.f;

    float dx = bbox[p];
    float dyv = bbox[HW + p];
    float dw = bbox[2 * HW + p];
    float dh = bbox[3 * HW + p];
    float dt = bbox[4 * HW + p];
    const float MR = 13.815510557964274f;
    dw = fminf(fmaxf(dw, -MR), MR);
    dh = fminf(fmaxf(dh, -MR), MR);
    float gx = dx * 32.f + ax;
    float gy = dyv * 32.f + ay;
    float gw = 32.f * expf(dw);
    float gh = 32.f * expf(dh);
    const float PI = 3.14159265358979323846f;
    float r = fmodf(dt + PI * 0.25f, PI);
    if (r < 0.f) r += PI;
    float ga = r - PI * 0.25f;
    refine_out[p * 5 + 0] = gx;
    refine_out[p * 5 + 1] = gy;
    refine_out[p * 5 + 2] = gw;
    refine_out[p * 5 + 3] = gh;
    refine_out[p * 5 + 4] = ga;
}

// ---------------- rotation-invariant max pooling on pair tensors ----------------
__global__ void maxpool8_kernel(const uint32_t* __restrict__ oh,
                                const uint32_t* __restrict__ ol,
                                unsigned short* __restrict__ ph,
                                unsigned short* __restrict__ pl) {
    int p = blockIdx.x * blockDim.x + threadIdx.x;
    int i = blockIdx.y;
    if (p >= HW) return;
    float m = -1e30f;
#pragma unroll
    for (int r2 = 0; r2 < 4; r2++) {
        size_t w = (size_t)(i * 4 + r2) * HW + p;
        uint32_t wh = oh[w], wl = ol[w];
        float v0 = half_of(wh, 0) + half_of(wl, 0);
        float v1 = half_of(wh, 1) + half_of(wl, 1);
        m = fmaxf(m, fmaxf(v0, v1));
    }
    size_t wo = ((size_t)(i >> 1) * HW + p) * 2 + (i & 1);
    unsigned short hb = bf16u(m);
    ph[wo] = hb;
    pl[wo] = bf16u(m - ubf(hb));
}

// ---------------- host orchestration ----------------
extern "C" void kernel_launch(void* const* d_in, const int* in_sizes, int n_in,
                              void* d_out, int out_size) {
    (void)in_sizes; (void)n_in; (void)out_size;

    const float* feats = (const float*)d_in[0];
    const float* fam_reg_w0 = (const float*)d_in[1];
    const float* fam_reg_b0 = (const float*)d_in[2];
    const float* fam_reg_w1 = (const float*)d_in[3];
    const float* fam_reg_b1 = (const float*)d_in[4];
    const float* fam_reg_hw = (const float*)d_in[5];
    const float* fam_reg_hb = (const float*)d_in[6];
    const float* fam_cls_w0 = (const float*)d_in[7];
    const float* fam_cls_b0 = (const float*)d_in[8];
    const float* fam_cls_w1 = (const float*)d_in[9];
    const float* fam_cls_b1 = (const float*)d_in[10];
    const float* fam_cls_hw = (const float*)d_in[11];
    const float* fam_cls_hb = (const float*)d_in[12];
    const float* align_w = (const float*)d_in[13];
    const float* align_b = (const float*)d_in[14];
    const float* or_w = (const float*)d_in[15];
    const float* or_b = (const float*)d_in[16];
    const float* odm_reg_w0 = (const float*)d_in[17];
    const float* odm_reg_b0 = (const float*)d_in[18];
    const float* odm_reg_w1 = (const float*)d_in[19];
    const float* odm_reg_b1 = (const float*)d_in[20];
    const float* odm_reg_hw = (const float*)d_in[21];
    const float* odm_reg_hb = (const float*)d_in[22];
    const float* odm_cls_w0 = (const float*)d_in[23];
    const float* odm_cls_b0 = (const float*)d_in[24];
    const float* odm_cls_w1 = (const float*)d_in[25];
    const float* odm_cls_b1 = (const float*)d_in[26];
    const float* odm_cls_hw = (const float*)d_in[27];
    const float* odm_cls_hb = (const float*)d_in[28];

    float* out = (float*)d_out;
    float* o_famcls = out;
    float* o_fambbox = out + 245760;
    float* o_odmcls = out + 327680;
    float* o_odmbbox = out + 573440;
    float* o_anchors = out + 655360;
    float* o_refine = out + 737280;

    float *b1, *b2, *wts, *hd, *hd2;
    unsigned char* wp;
    uint32_t *p0h, *p0l, *p1h, *p1l, *p2h, *p2l, *p3h, *p3l, *pdh, *pdl;
    cudaGetSymbolAddress((void**)&b1, g_b1);
    cudaGetSymbolAddress((void**)&b2, g_b2);
    cudaGetSymbolAddress((void**)&hd, g_head);
    cudaGetSymbolAddress((void**)&hd2, g_head2);
    cudaGetSymbolAddress((void**)&wts, g_wt_small);
    cudaGetSymbolAddress((void**)&wp, g_wpack);
    cudaGetSymbolAddress((void**)&p0h, g_p0h);
    cudaGetSymbolAddress((void**)&p0l, g_p0l);
    cudaGetSymbolAddress((void**)&p1h, g_p1h);
    cudaGetSymbolAddress((void**)&p1l, g_p1l);
    cudaGetSymbolAddress((void**)&p2h, g_p2h);
    cudaGetSymbolAddress((void**)&p2l, g_p2l);
    cudaGetSymbolAddress((void**)&p3h, g_p3h);
    cudaGetSymbolAddress((void**)&p3l, g_p3l);
    cudaGetSymbolAddress((void**)&pdh, g_pdh);
    cudaGetSymbolAddress((void**)&pdl, g_pdl);

    cudaFuncSetAttribute(conv_hmma_kernel, cudaFuncAttributeMaxDynamicSharedMemorySize, SMEMH);
    cudaFuncSetAttribute(conv_deform_kernel, cudaFuncAttributeMaxDynamicSharedMemorySize, SMEMD);

    // side stream + fork/join events (created per call; kernel_launch runs only
    // a couple of times, so the tiny host-side leak is acceptable and avoids
    // destroying objects that participate in an ongoing graph capture)
    cudaStream_t s1;
    cudaEvent_t ev0, ev1, ev2, ev3;
    cudaStreamCreateWithFlags(&s1, cudaStreamNonBlocking);
    cudaEventCreateWithFlags(&ev0, cudaEventDisableTiming);
    cudaEventCreateWithFlags(&ev1, cudaEventDisableTiming);
    cudaEventCreateWithFlags(&ev2, cudaEventDisableTiming);
    cudaEventCreateWithFlags(&ev3, cudaEventDisableTiming);

    const size_t SLOT = 36 * 65536;

    // ---- prologue (stream 0): cvt + repacks ----
    cvt_pair_kernel<<<8192, 256>>>(feats, p0h, p0l, 128 * HW);
    {
        WPtrs P;
        P.w[0] = fam_reg_w0; P.w[1] = fam_reg_w1; P.w[2] = fam_cls_w0; P.w[3] = fam_cls_w1;
        P.w[4] = align_w; P.w[5] = odm_cls_w1; P.w[6] = odm_reg_w0; P.w[7] = odm_reg_w1;
        P.w[8] = odm_cls_w0;
        repack_all_kernel<<<(8 * 36 * 16384 + 9 * 16384 + 255) / 256, 256>>>(P, wp);
    }
    repack_or_tc_kernel<<<2304, 256>>>(or_w, wp);
    repack_heads_kernel<<<320, 256>>>(fam_reg_hw, fam_cls_hw, odm_cls_hw, odm_reg_hw, wts);

    // ---- fork 1: FAM reg (stream 0) || FAM cls (s1) ----
    cudaEventRecord(ev0, 0);
    cudaStreamWaitEvent(s1, ev0, 0);

    // stream 0: FAM reg chain -> fambbox, then decode
    conv_hmma_kernel<<<128, 256, SMEMH>>>(wp + 0 * SLOT, p0h, p0l, fam_reg_b0, b1,
                                          (unsigned short*)p1h, (unsigned short*)p1l,
                                          256, 1, 1, 0, 1);
    conv_hmma_kernel<<<128, 256, SMEMH>>>(wp + 1 * SLOT, p1h, p1l, fam_reg_b1, b1,
                                          (unsigned short*)p3h, (unsigned short*)p3l,
                                          256, 1, 1, 1, 0);
    head_part_kernel<<<dim3(128, 1), 128>>>(wts + 0, b1, hd, 256, 1);
    head_reduce_kernel<<<(5 * HW + 255) / 256, 256>>>(hd, fam_reg_hb, o_fambbox, 5, 1);
    decode_kernel<<<HW / 256, 256>>>(o_fambbox, o_anchors, o_refine);

    // s1: FAM cls chain -> famcls
    conv_hmma_kernel<<<128, 256, SMEMH, s1>>>(wp + 2 * SLOT, p0h, p0l, fam_cls_b0, b2,
                                              (unsigned short*)p2h, (unsigned short*)p2l,
                                              256, 1, 1, 0, 1);
    conv_hmma_kernel<<<128, 256, SMEMH, s1>>>(wp + 3 * SLOT, p2h, p2l, fam_cls_b1, b2,
                                              (unsigned short*)p3h, (unsigned short*)p3l,
                                              256, 1, 1, 1, 0);
    head_part_kernel<<<dim3(128, 1), 128, 0, s1>>>(wts + 4096, b2, hd2, 256, 1);
    head_reduce_kernel<<<(15 * HW + 255) / 256, 256, 0, s1>>>(hd2, fam_cls_hb, o_famcls, 15, 1);

    // join 1
    cudaEventRecord(ev1, s1);
    cudaStreamWaitEvent(0, ev1, 0);

    // ---- middle (stream 0): deform align -> P1, OR conv -> P2, pool -> PD ----
    conv_deform_kernel<<<128, 256, SMEMD>>>(wp + 4 * SLOT, feats, o_refine, align_b,
                                            (unsigned short*)p1h, (unsigned short*)p1l);
    conv_hmma_kernel<<<128, 256, SMEMH>>>(wp + 8 * SLOT, p1h, p1l, or_b, b1,
                                          (unsigned short*)p2h, (unsigned short*)p2l,
                                          256, 0, 8, 0, 1);
    {
        dim3 g(HW / 256, 32);
        maxpool8_kernel<<<g, 256>>>(p2h, p2l, (unsigned short*)pdh, (unsigned short*)pdl);
    }

    // ---- fork 2: ODM cls (stream 0) || ODM reg (s1) ----
    cudaEventRecord(ev2, 0);
    cudaStreamWaitEvent(s1, ev2, 0);

    // stream 0: ODM cls chain: PD -> P3 -> b1 -> odmcls
    conv_hmma_kernel<<<128, 256, SMEMH>>>(wp + 9 * SLOT, pdh, pdl, odm_cls_b0, b1,
                                          (unsigned short*)p3h, (unsigned short*)p3l,
                                          32, 1, 1, 0, 1);
    conv_hmma_kernel<<<128, 256, SMEMH>>>(wp + 5 * SLOT, p3h, p3l, odm_cls_b1, b1,
                                          (unsigned short*)p1h, (unsigned short*)p1l,
                                          256, 1, 1, 1, 0);
    head_part_kernel<<<dim3(128, 9), 128>>>(wts + 8192, b1, hd, 256, 9);
    head_reduce_kernel<<<(15 * HW + 255) / 256, 256>>>(hd, odm_cls_hb, o_odmcls, 15, 9);

    // s1: ODM reg chain: P2 -> P0 -> b2 -> odmbbox (buffers disjoint from cls chain)
    conv_hmma_kernel<<<128, 256, SMEMH, s1>>>(wp + 6 * SLOT, p2h, p2l, odm_reg_b0, b2,
                                              (unsigned short*)p0h, (unsigned short*)p0l,
                                              256, 1, 1, 0, 1);
    conv_hmma_kernel<<<128, 256, SMEMH, s1>>>(wp + 7 * SLOT, p0h, p0l, odm_reg_b1, b2,
                                              (unsigned short*)p1h, (unsigned short*)p1l,
                                              256, 1, 1, 1, 0);
    head_part_kernel<<<dim3(128, 9), 128, 0, s1>>>(wts + 45056, b2, hd2, 256, 9);
    head_reduce_kernel<<<(5 * HW + 255) / 256, 256, 0, s1>>>(hd2, odm_reg_hb, o_odmbbox, 5, 9);

    // join 2
    cudaEventRecord(ev3, s1);
    cudaStreamWaitEvent(0, ev3, 0);
}